// round 10
// baseline (speedup 1.0000x reference)
#include <cuda_runtime.h>
#include <cuda_fp16.h>
#include <cstdint>

#define NN 50000
#define EE 800000

// ---------------- scratch (static device globals; no allocs) ----------------
__device__ __half g_m2hi[NN * 128], g_m2lo[NN * 128];
__device__ __half g_qp1[NN * 256];   // fp16: [node][0:128]=q1, [128:256]=p1
__device__ __half g_qp2[NN * 128];   // fp16: [node][0:64]=q2, [64:128]=p2
__device__ __half g_w0t[128 * 128];
__device__ __half g_wqp1t[256 * 128];
__device__ __half g_wqp2t[128 * 128];
__device__ float g_bqp1[256];
__device__ float g_bqp2[128];
__device__ int   g_rowptr[NN + 1];
__device__ int   g_cursor[NN];
__device__ int   g_esrc[EE];

__device__ __forceinline__ float gelu_f(float x) {
    return 0.5f * x * (1.0f + erff(x * 0.70710678118654752440f));
}
__device__ __forceinline__ void split_h(float v, __half& hi, __half& lo) {
    hi = __float2half_rn(v);
    lo = __float2half_rn(v - __half2float(hi));
}
__device__ __forceinline__ uint32_t smem_u32(const void* p) {
    uint32_t a;
    asm("{ .reg .u64 t; cvta.to.shared.u64 t, %1; cvt.u32.u64 %0, t; }" : "=r"(a) : "l"(p));
    return a;
}
__device__ __forceinline__ void ldsm4(uint32_t& r0, uint32_t& r1, uint32_t& r2, uint32_t& r3, uint32_t addr) {
    asm volatile("ldmatrix.sync.aligned.m8n8.x4.shared.b16 {%0,%1,%2,%3}, [%4];"
                 : "=r"(r0), "=r"(r1), "=r"(r2), "=r"(r3) : "r"(addr));
}
__device__ __forceinline__ void mma_f16(float* c, const uint32_t* a, const uint32_t* b) {
    asm volatile(
        "mma.sync.aligned.m16n8k16.row.col.f32.f16.f16.f32 "
        "{%0,%1,%2,%3}, {%4,%5,%6,%7}, {%8,%9}, {%0,%1,%2,%3};"
        : "+f"(c[0]), "+f"(c[1]), "+f"(c[2]), "+f"(c[3])
        : "r"(a[0]), "r"(a[1]), "r"(a[2]), "r"(a[3]), "r"(b[0]), "r"(b[1]));
}
__device__ __forceinline__ void cp16(uint32_t saddr, const void* gaddr) {
    asm volatile("cp.async.cg.shared.global [%0], [%1], 16;" :: "r"(saddr), "l"(gaddr) : "memory");
}
// unpack 8 fp16 (uint4) -> 8 floats
__device__ __forceinline__ void unp8(uint4 v, float* f) {
    __half2* h = (__half2*)&v;
#pragma unroll
    for (int j = 0; j < 4; j++) {
        float2 x = __half22float2(h[j]);
        f[2 * j] = x.x; f[2 * j + 1] = x.y;
    }
}

#define ASTRIDE 136
#define ABUF (128 * ASTRIDE * 2)   // 34816 B per buffer

__device__ __forceinline__ void mainloop_f16(
    uint32_t ah_base, uint32_t al_base, uint32_t bh_base,
    int wm, int wn, int lane, float acc[2][8][4])
{
    const int a_r = (lane & 15);
    const int a_c = (lane >> 4) * 8;
    const int b_r = (lane & 7) + ((lane >> 4) << 3);
    const int b_c = ((lane >> 3) & 1) * 8;
#pragma unroll
    for (int ks = 0; ks < 8; ks++) {
        const int k0 = ks * 16;
        uint32_t ah[2][4], al[2][4];
#pragma unroll
        for (int mt = 0; mt < 2; mt++) {
            uint32_t off = (uint32_t)((wm * 32 + mt * 16 + a_r) * ASTRIDE + k0 + a_c) * 2;
            ldsm4(ah[mt][0], ah[mt][1], ah[mt][2], ah[mt][3], ah_base + off);
            ldsm4(al[mt][0], al[mt][1], al[mt][2], al[mt][3], al_base + off);
        }
        uint32_t bh[8][2];
#pragma unroll
        for (int ng = 0; ng < 4; ng++) {
            uint32_t off = (uint32_t)((wn * 64 + ng * 16 + b_r) * ASTRIDE + k0 + b_c) * 2;
            ldsm4(bh[2 * ng][0], bh[2 * ng][1], bh[2 * ng + 1][0], bh[2 * ng + 1][1], bh_base + off);
        }
#pragma unroll
        for (int mt = 0; mt < 2; mt++)
#pragma unroll
            for (int nt = 0; nt < 8; nt++) {
                mma_f16(acc[mt][nt], ah[mt], bh[nt]);
                mma_f16(acc[mt][nt], al[mt], bh[nt]);
            }
    }
}

// ---------------- CSR build ----------------
__global__ void zero_k() {
    int i = blockIdx.x * blockDim.x + threadIdx.x;
    if (i < NN) g_cursor[i] = 0;
}
__global__ void hist_k(const int* __restrict__ dst) {
    int e = blockIdx.x * blockDim.x + threadIdx.x;
    if (e < EE) atomicAdd(&g_cursor[dst[e]], 1);
}
__global__ __launch_bounds__(1024) void scan_k() {
    __shared__ int warpsum[32];
    __shared__ int s_carry;
    __shared__ int s_tot;
    int tid = threadIdx.x, lane = tid & 31, wid = tid >> 5;
    if (tid == 0) s_carry = 0;
    __syncthreads();
    for (int base = 0; base < NN; base += 8192) {
        int idx0 = base + tid * 8;
        int v[8]; int tot = 0;
#pragma unroll
        for (int j = 0; j < 8; j++) {
            int id = idx0 + j;
            v[j] = (id < NN) ? g_cursor[id] : 0;
            tot += v[j];
        }
        int incl = tot;
#pragma unroll
        for (int off = 1; off < 32; off <<= 1) {
            int t = __shfl_up_sync(0xffffffffu, incl, off);
            if (lane >= off) incl += t;
        }
        if (lane == 31) warpsum[wid] = incl;
        __syncthreads();
        if (wid == 0) {
            int w = warpsum[lane];
            int wi = w;
#pragma unroll
            for (int off = 1; off < 32; off <<= 1) {
                int t = __shfl_up_sync(0xffffffffu, wi, off);
                if (lane >= off) wi += t;
            }
            warpsum[lane] = wi - w;
            if (lane == 31) s_tot = wi;
        }
        __syncthreads();
        int run = s_carry + warpsum[wid] + (incl - tot);
#pragma unroll
        for (int j = 0; j < 8; j++) {
            int id = idx0 + j;
            if (id < NN) { g_rowptr[id] = run; g_cursor[id] = 0; }
            run += v[j];
        }
        __syncthreads();
        if (tid == 0) s_carry += s_tot;
        __syncthreads();
    }
    if (threadIdx.x == 0) g_rowptr[NN] = s_carry;
}
__global__ void scatter_k(const int* __restrict__ src, const int* __restrict__ dst) {
    int e = blockIdx.x * blockDim.x + threadIdx.x;
    if (e < EE) {
        int d = dst[e];
        int pos = g_rowptr[d] + atomicAdd(&g_cursor[d], 1);
        g_esrc[pos] = src[e];
    }
}

// ---------------- conversions ----------------
__global__ void convw_k(const float* __restrict__ Wa, const float* __restrict__ Wb,
                        const float* __restrict__ ba, const float* __restrict__ bb,
                        __half* __restrict__ Wt, float* __restrict__ bc, int na, int nb) {
    int nc = na + nb;
    int i = blockIdx.x * blockDim.x + threadIdx.x;
    if (i < nc * 128) {
        int n = i >> 7, k = i & 127;
        float v = (n < na) ? Wa[(size_t)k * na + n] : Wb[(size_t)k * nb + (n - na)];
        Wt[i] = __float2half_rn(v);
    }
    if (bc && i < nc) bc[i] = (i < na) ? ba[i] : bb[i - na];
}

// ---------------- fused layer-1: qp1 = gelu(x@W0+b0) @ Wqp1 + bqp1 (fp16 out) --
__global__ __launch_bounds__(256, 2) void gemm_l1(
    const float* __restrict__ x, const __half* __restrict__ W0t,
    const float* __restrict__ b0, const __half* __restrict__ Wqp1t,
    const float* __restrict__ bqp1, __half* __restrict__ qp1, int M)
{
    extern __shared__ char sm[];
    char* AH = sm;
    char* AL = sm + ABUF;
    char* BH = sm + 2 * ABUF;

    const int tid = threadIdx.x;
    const int warp = tid >> 5, lane = tid & 31;
    const int wm = warp >> 1, wn = warp & 1;
    const int rowBase = blockIdx.x * 128;

    const uint32_t ah_base = smem_u32(AH);
    const uint32_t al_base = smem_u32(AL);
    const uint32_t bh_base = smem_u32(BH);

#pragma unroll
    for (int it = 0; it < 8; it++) {
        int idx = tid + it * 256;
        int row = idx >> 4, ch = idx & 15;
        uint32_t so = (uint32_t)(row * ASTRIDE + ch * 8) * 2;
        cp16(bh_base + so, W0t + (size_t)row * 128 + ch * 8);
    }
    asm volatile("cp.async.commit_group;" ::: "memory");
#pragma unroll
    for (int it = 0; it < 8; it++) {
        int idx = tid + it * 256;
        int row = idx >> 4, ch = idx & 15;
        int gr = rowBase + row; if (gr >= M) gr = M - 1;
        float4 v0 = *(const float4*)(x + (size_t)gr * 128 + ch * 8);
        float4 v1 = *(const float4*)(x + (size_t)gr * 128 + ch * 8 + 4);
        __half hh[8], ll[8];
        split_h(v0.x, hh[0], ll[0]); split_h(v0.y, hh[1], ll[1]);
        split_h(v0.z, hh[2], ll[2]); split_h(v0.w, hh[3], ll[3]);
        split_h(v1.x, hh[4], ll[4]); split_h(v1.y, hh[5], ll[5]);
        split_h(v1.z, hh[6], ll[6]); split_h(v1.w, hh[7], ll[7]);
        uint32_t so = (uint32_t)(row * ASTRIDE + ch * 8) * 2;
        *(uint4*)(AH + so) = *(const uint4*)hh;
        *(uint4*)(AL + so) = *(const uint4*)ll;
    }
    asm volatile("cp.async.wait_group 0;" ::: "memory");
    __syncthreads();

    float acc[2][8][4];
#pragma unroll
    for (int i = 0; i < 2; i++)
#pragma unroll
        for (int j = 0; j < 8; j++)
#pragma unroll
            for (int k = 0; k < 4; k++) acc[i][j][k] = 0.f;

    mainloop_f16(ah_base, al_base, bh_base, wm, wn, lane, acc);
    __syncthreads();

#pragma unroll
    for (int it = 0; it < 8; it++) {
        int idx = tid + it * 256;
        int row = idx >> 4, ch = idx & 15;
        uint32_t so = (uint32_t)(row * ASTRIDE + ch * 8) * 2;
        cp16(bh_base + so, Wqp1t + (size_t)row * 128 + ch * 8);
    }
    asm volatile("cp.async.commit_group;" ::: "memory");

#pragma unroll
    for (int mt = 0; mt < 2; mt++)
#pragma unroll
        for (int nt = 0; nt < 8; nt++) {
            int c = wn * 64 + nt * 8 + (lane & 3) * 2;
            float bb0 = b0[c], bb1 = b0[c + 1];
#pragma unroll
            for (int h = 0; h < 2; h++) {
                int r = wm * 32 + mt * 16 + (lane >> 2) + h * 8;
                float v0 = gelu_f(acc[mt][nt][2 * h + 0] + bb0);
                float v1 = gelu_f(acc[mt][nt][2 * h + 1] + bb1);
                __half h0, l0, h1, l1;
                split_h(v0, h0, l0);
                split_h(v1, h1, l1);
                uint32_t so = (uint32_t)(r * ASTRIDE + c) * 2;
                __half2 hh; hh.x = h0; hh.y = h1;
                __half2 ll; ll.x = l0; ll.y = l1;
                *(__half2*)(AH + so) = hh;
                *(__half2*)(AL + so) = ll;
            }
        }
    asm volatile("cp.async.wait_group 0;" ::: "memory");
    __syncthreads();

#pragma unroll
    for (int cb = 0; cb < 2; cb++) {
#pragma unroll
        for (int i = 0; i < 2; i++)
#pragma unroll
            for (int j = 0; j < 8; j++)
#pragma unroll
                for (int k = 0; k < 4; k++) acc[i][j][k] = 0.f;
        mainloop_f16(ah_base, al_base, bh_base, wm, wn, lane, acc);

        if (cb == 0) {
            __syncthreads();
#pragma unroll
            for (int it = 0; it < 8; it++) {
                int idx = tid + it * 256;
                int row = idx >> 4, ch = idx & 15;
                uint32_t so = (uint32_t)(row * ASTRIDE + ch * 8) * 2;
                cp16(bh_base + so, Wqp1t + (size_t)(128 + row) * 128 + ch * 8);
            }
            asm volatile("cp.async.commit_group;" ::: "memory");
        }

#pragma unroll
        for (int mt = 0; mt < 2; mt++)
#pragma unroll
            for (int nt = 0; nt < 8; nt++) {
                int c = cb * 128 + wn * 64 + nt * 8 + (lane & 3) * 2;
                float bb0 = bqp1[c], bb1 = bqp1[c + 1];
#pragma unroll
                for (int h = 0; h < 2; h++) {
                    int r = rowBase + wm * 32 + mt * 16 + (lane >> 2) + h * 8;
                    if (r < M) {
                        __half2 o;
                        o.x = __float2half_rn(acc[mt][nt][2 * h + 0] + bb0);
                        o.y = __float2half_rn(acc[mt][nt][2 * h + 1] + bb1);
                        *(__half2*)(qp1 + (size_t)r * 256 + c) = o;
                    }
                }
            }
        if (cb == 0) {
            asm volatile("cp.async.wait_group 0;" ::: "memory");
            __syncthreads();
        }
    }
}

// ---------------- layer-2 GEMM (reads m2 hi/lo, writes fp16 qp2) -------------
__global__ __launch_bounds__(256, 2) void gemm_mma(
    const __half* __restrict__ Ahi, const __half* __restrict__ Alo,
    const __half* __restrict__ Bh, const float* __restrict__ bias,
    __half* __restrict__ Cf, int M, int ncols)
{
    extern __shared__ char sm[];
    char* AH = sm;
    char* AL = sm + ABUF;
    char* BH = sm + 2 * ABUF;

    const int tid = threadIdx.x;
    const int warp = tid >> 5, lane = tid & 31;
    const int wm = warp >> 1, wn = warp & 1;
    const int rowBase = blockIdx.x * 128;

    const uint32_t ah_base = smem_u32(AH);
    const uint32_t al_base = smem_u32(AL);
    const uint32_t bh_base = smem_u32(BH);

#pragma unroll
    for (int it = 0; it < 8; it++) {
        int idx = tid + it * 256;
        int row = idx >> 4, ch = idx & 15;
        int gr = rowBase + row; if (gr >= M) gr = M - 1;
        uint32_t so = (uint32_t)(row * ASTRIDE + ch * 8) * 2;
        cp16(ah_base + so, Ahi + (size_t)gr * 128 + ch * 8);
        cp16(al_base + so, Alo + (size_t)gr * 128 + ch * 8);
        cp16(bh_base + so, Bh + (size_t)row * 128 + ch * 8);
    }
    asm volatile("cp.async.commit_group;" ::: "memory");
    asm volatile("cp.async.wait_group 0;" ::: "memory");
    __syncthreads();

    float acc[2][8][4];
#pragma unroll
    for (int i = 0; i < 2; i++)
#pragma unroll
        for (int j = 0; j < 8; j++)
#pragma unroll
            for (int k = 0; k < 4; k++) acc[i][j][k] = 0.f;
    mainloop_f16(ah_base, al_base, bh_base, wm, wn, lane, acc);

#pragma unroll
    for (int mt = 0; mt < 2; mt++)
#pragma unroll
        for (int nt = 0; nt < 8; nt++) {
            int c = wn * 64 + nt * 8 + (lane & 3) * 2;
            float b0 = bias[c], b1 = bias[c + 1];
#pragma unroll
            for (int h = 0; h < 2; h++) {
                int r = rowBase + wm * 32 + mt * 16 + (lane >> 2) + h * 8;
                if (r < M) {
                    __half2 o;
                    o.x = __float2half_rn(acc[mt][nt][2 * h + 0] + b0);
                    o.y = __float2half_rn(acc[mt][nt][2 * h + 1] + b1);
                    *(__half2*)(Cf + (size_t)r * ncols + c) = o;
                }
            }
        }
}

// ---------------- edge kernels: 4 edge-slots x 8 lanes per warp ---------------
// layer1: d=128. lane = (g<<3)|t: group g=0..3 handles edge i+g, lane covers dims t*16..+15.
__global__ __launch_bounds__(256) void edge128_k(
    const __half* __restrict__ qp, const float* __restrict__ a,
    const float* __restrict__ bg)
{
    int gw = (blockIdx.x * 256 + threadIdx.x) >> 5;
    if (gw >= NN) return;
    int lane = threadIdx.x & 31;
    int g = lane >> 3, t = lane & 7;
    const int d0 = t * 16;

    float qv[16], av[16];
    {
        const uint4* qptr = (const uint4*)(qp + (size_t)gw * 256 + d0);
        unp8(qptr[0], qv); unp8(qptr[1], qv + 8);
#pragma unroll
        for (int j = 0; j < 4; j++) {
            float4 va = *(const float4*)(a + d0 + 4 * j);
            av[4 * j] = va.x; av[4 * j + 1] = va.y; av[4 * j + 2] = va.z; av[4 * j + 3] = va.w;
        }
    }
    float agg[16];
#pragma unroll
    for (int d = 0; d < 16; d++) agg[d] = 0.f;
    float denom = 0.f;

    int start = g_rowptr[gw], end = g_rowptr[gw + 1];
    int nIter = (end - start + 3) >> 2;
    for (int it = 0; it < nIter; it++) {
        int e = start + it * 4 + g;
        bool valid = e < end;
        int s_idx = valid ? g_esrc[e] : 0;
        const uint4* pptr = (const uint4*)(qp + (size_t)s_idx * 256 + 128 + d0);
        float pv[16];
        unp8(pptr[0], pv); unp8(pptr[1], pv + 8);
        float s = 0.f;
#pragma unroll
        for (int d = 0; d < 16; d++) {
            float tx = qv[d] + pv[d];
            tx = tx > 0.f ? tx : 0.2f * tx;
            s = fmaf(tx, av[d], s);
        }
        s += __shfl_xor_sync(0xffffffffu, s, 4);
        s += __shfl_xor_sync(0xffffffffu, s, 2);
        s += __shfl_xor_sync(0xffffffffu, s, 1);
        float es = valid ? __expf(s) : 0.f;
        denom += es;
#pragma unroll
        for (int d = 0; d < 16; d++) agg[d] = fmaf(es, pv[d], agg[d]);
    }
    // combine the 4 edge-slot groups
    denom += __shfl_xor_sync(0xffffffffu, denom, 8);
    denom += __shfl_xor_sync(0xffffffffu, denom, 16);
#pragma unroll
    for (int d = 0; d < 16; d++) {
        agg[d] += __shfl_xor_sync(0xffffffffu, agg[d], 8);
        agg[d] += __shfl_xor_sync(0xffffffffu, agg[d], 16);
    }
    if (g == 0) {
        float inv = denom > 0.f ? 1.0f / denom : 0.f;
        __half hh[16], ll[16];
#pragma unroll
        for (int d = 0; d < 16; d++) {
            float o = gelu_f(fmaf(agg[d], inv, bg[d0 + d]));
            split_h(o, hh[d], ll[d]);
        }
        uint4* oh = (uint4*)(g_m2hi + (size_t)gw * 128 + d0);
        uint4* ol = (uint4*)(g_m2lo + (size_t)gw * 128 + d0);
        oh[0] = ((const uint4*)hh)[0]; oh[1] = ((const uint4*)hh)[1];
        ol[0] = ((const uint4*)ll)[0]; ol[1] = ((const uint4*)ll)[1];
    }
}

// layer2: d=64. lane covers dims t*8..+7; out = h2 + b_out (fp32 out).
__global__ __launch_bounds__(256) void edge64_k(
    const __half* __restrict__ qp, const float* __restrict__ a,
    const float* __restrict__ bo, float* __restrict__ out)
{
    int gw = (blockIdx.x * 256 + threadIdx.x) >> 5;
    if (gw >= NN) return;
    int lane = threadIdx.x & 31;
    int g = lane >> 3, t = lane & 7;
    const int d0 = t * 8;

    float qv[8], av[8];
    {
        uint4 q = *(const uint4*)(qp + (size_t)gw * 128 + d0);
        unp8(q, qv);
#pragma unroll
        for (int j = 0; j < 2; j++) {
            float4 va = *(const float4*)(a + d0 + 4 * j);
            av[4 * j] = va.x; av[4 * j + 1] = va.y; av[4 * j + 2] = va.z; av[4 * j + 3] = va.w;
        }
    }
    float agg[8];
#pragma unroll
    for (int d = 0; d < 8; d++) agg[d] = 0.f;
    float denom = 0.f;

    int start = g_rowptr[gw], end = g_rowptr[gw + 1];
    int nIter = (end - start + 3) >> 2;
    for (int it = 0; it < nIter; it++) {
        int e = start + it * 4 + g;
        bool valid = e < end;
        int s_idx = valid ? g_esrc[e] : 0;
        uint4 praw = *(const uint4*)(qp + (size_t)s_idx * 128 + 64 + d0);
        float pv[8];
        unp8(praw, pv);
        float s = 0.f;
#pragma unroll
        for (int d = 0; d < 8; d++) {
            float tx = qv[d] + pv[d];
            tx = tx > 0.f ? tx : 0.2f * tx;
            s = fmaf(tx, av[d], s);
        }
        s += __shfl_xor_sync(0xffffffffu, s, 4);
        s += __shfl_xor_sync(0xffffffffu, s, 2);
        s += __shfl_xor_sync(0xffffffffu, s, 1);
        float es = valid ? __expf(s) : 0.f;
        denom += es;
#pragma unroll
        for (int d = 0; d < 8; d++) agg[d] = fmaf(es, pv[d], agg[d]);
    }
    denom += __shfl_xor_sync(0xffffffffu, denom, 8);
    denom += __shfl_xor_sync(0xffffffffu, denom, 16);
#pragma unroll
    for (int d = 0; d < 8; d++) {
        agg[d] += __shfl_xor_sync(0xffffffffu, agg[d], 8);
        agg[d] += __shfl_xor_sync(0xffffffffu, agg[d], 16);
    }
    if (g == 0) {
        float inv = denom > 0.f ? 1.0f / denom : 0.f;
        float o[8];
#pragma unroll
        for (int d = 0; d < 8; d++) o[d] = fmaf(agg[d], inv, bo[d0 + d]);
        float4* op = (float4*)(out + (size_t)gw * 64 + d0);
        op[0] = make_float4(o[0], o[1], o[2], o[3]);
        op[1] = make_float4(o[4], o[5], o[6], o[7]);
    }
}

// ---------------- launch ----------------
extern "C" void kernel_launch(void* const* d_in, const int* in_sizes, int n_in,
                              void* d_out, int out_size)
{
    const float* x    = (const float*)d_in[0];
    const float* W0   = (const float*)d_in[1];
    const float* b0   = (const float*)d_in[2];
    const float* Wq1  = (const float*)d_in[3];
    const float* bq1  = (const float*)d_in[4];
    const float* Wp1  = (const float*)d_in[5];
    const float* bp1  = (const float*)d_in[6];
    const float* a1   = (const float*)d_in[7];
    const float* bg2  = (const float*)d_in[8];
    const float* Wq2  = (const float*)d_in[9];
    const float* bq2  = (const float*)d_in[10];
    const float* Wp2  = (const float*)d_in[11];
    const float* bp2  = (const float*)d_in[12];
    const float* a2   = (const float*)d_in[13];
    const float* bout = (const float*)d_in[14];
    const int*   src  = (const int*)d_in[15];
    const int*   dst  = (const int*)d_in[16];
    float* out = (float*)d_out;

    __half *m2hi, *m2lo, *w0t, *wqp1t, *wqp2t, *qp1, *qp2;
    float *bqp1, *bqp2;
    cudaGetSymbolAddress((void**)&m2hi, g_m2hi); cudaGetSymbolAddress((void**)&m2lo, g_m2lo);
    cudaGetSymbolAddress((void**)&w0t, g_w0t);
    cudaGetSymbolAddress((void**)&wqp1t, g_wqp1t);
    cudaGetSymbolAddress((void**)&wqp2t, g_wqp2t);
    cudaGetSymbolAddress((void**)&qp1, g_qp1); cudaGetSymbolAddress((void**)&qp2, g_qp2);
    cudaGetSymbolAddress((void**)&bqp1, g_bqp1); cudaGetSymbolAddress((void**)&bqp2, g_bqp2);

    constexpr int SMEM = 3 * ABUF;   // 104448 B
    cudaFuncSetAttribute(gemm_l1, cudaFuncAttributeMaxDynamicSharedMemorySize, SMEM);
    cudaFuncSetAttribute(gemm_mma, cudaFuncAttributeMaxDynamicSharedMemorySize, SMEM);

    // ---- fork: CSR build + layer-2 weight conversion on side stream ----
    cudaStream_t s2;
    cudaStreamCreateWithFlags(&s2, cudaStreamNonBlocking);
    cudaEvent_t evFork, evJoin;
    cudaEventCreateWithFlags(&evFork, cudaEventDisableTiming);
    cudaEventCreateWithFlags(&evJoin, cudaEventDisableTiming);

    cudaEventRecord(evFork, 0);
    cudaStreamWaitEvent(s2, evFork, 0);
    zero_k<<<(NN + 255) / 256, 256, 0, s2>>>();
    hist_k<<<(EE + 255) / 256, 256, 0, s2>>>(dst);
    scan_k<<<1, 1024, 0, s2>>>();
    scatter_k<<<(EE + 255) / 256, 256, 0, s2>>>(src, dst);
    convw_k<<<(128 * 128 + 255) / 256, 256, 0, s2>>>(Wq2, Wp2, bq2, bp2, wqp2t, bqp2, 64, 64);
    cudaEventRecord(evJoin, s2);

    // ---- main chain ----
    convw_k<<<(128 * 128 + 255) / 256, 256>>>(W0, W0, b0, b0, w0t, nullptr, 128, 0);
    convw_k<<<(256 * 128 + 255) / 256, 256>>>(Wq1, Wp1, bq1, bp1, wqp1t, bqp1, 128, 128);

    const int MB = (NN + 127) / 128;

    gemm_l1<<<MB, 256, SMEM>>>(x, w0t, b0, wqp1t, bqp1, qp1, NN);

    cudaStreamWaitEvent(0, evJoin, 0);
    edge128_k<<<(NN * 32 + 255) / 256, 256>>>(qp1, a1, bg2);       // m2 (fp16 hi/lo)

    gemm_mma<<<MB, 256, SMEM>>>(m2hi, m2lo, wqp2t, bqp2, qp2, NN, 128);
    edge64_k<<<(NN * 32 + 255) / 256, 256>>>(qp2, a2, bout, out);
}

// round 11
// speedup vs baseline: 1.0239x; 1.0239x over previous
#include <cuda_runtime.h>
#include <cuda_fp16.h>
#include <cstdint>

#define NN 50000
#define EE 800000

// ---------------- scratch (static device globals; no allocs) ----------------
__device__ __half g_m2hi[NN * 128], g_m2lo[NN * 128];
__device__ float g_qp1[NN * 256];   // [node][0:128]=q1, [128:256]=p1
__device__ float g_qp2[NN * 128];   // [node][0:64]=q2, [64:128]=p2
__device__ __half g_w0t[128 * 128];
__device__ __half g_wqp1t[256 * 128];
__device__ __half g_wqp2t[128 * 128];
__device__ float g_bqp1[256];
__device__ float g_bqp2[128];
__device__ int   g_rowptr[NN + 1];
__device__ int   g_cursor[NN];
__device__ int   g_esrc[EE];

__device__ __forceinline__ float gelu_f(float x) {
    return 0.5f * x * (1.0f + erff(x * 0.70710678118654752440f));
}
__device__ __forceinline__ void split_h(float v, __half& hi, __half& lo) {
    hi = __float2half_rn(v);
    lo = __float2half_rn(v - __half2float(hi));
}
__device__ __forceinline__ uint32_t smem_u32(const void* p) {
    uint32_t a;
    asm("{ .reg .u64 t; cvta.to.shared.u64 t, %1; cvt.u32.u64 %0, t; }" : "=r"(a) : "l"(p));
    return a;
}
__device__ __forceinline__ void ldsm4(uint32_t& r0, uint32_t& r1, uint32_t& r2, uint32_t& r3, uint32_t addr) {
    asm volatile("ldmatrix.sync.aligned.m8n8.x4.shared.b16 {%0,%1,%2,%3}, [%4];"
                 : "=r"(r0), "=r"(r1), "=r"(r2), "=r"(r3) : "r"(addr));
}
__device__ __forceinline__ void mma_f16(float* c, const uint32_t* a, const uint32_t* b) {
    asm volatile(
        "mma.sync.aligned.m16n8k16.row.col.f32.f16.f16.f32 "
        "{%0,%1,%2,%3}, {%4,%5,%6,%7}, {%8,%9}, {%0,%1,%2,%3};"
        : "+f"(c[0]), "+f"(c[1]), "+f"(c[2]), "+f"(c[3])
        : "r"(a[0]), "r"(a[1]), "r"(a[2]), "r"(a[3]), "r"(b[0]), "r"(b[1]));
}
__device__ __forceinline__ void cp16(uint32_t saddr, const void* gaddr) {
    asm volatile("cp.async.cg.shared.global [%0], [%1], 16;" :: "r"(saddr), "l"(gaddr) : "memory");
}

#define ASTRIDE 136
#define ABUF (128 * ASTRIDE * 2)   // 34816 B per buffer

__device__ __forceinline__ void mainloop_f16(
    uint32_t ah_base, uint32_t al_base, uint32_t bh_base,
    int wm, int wn, int lane, float acc[2][8][4])
{
    const int a_r = (lane & 15);
    const int a_c = (lane >> 4) * 8;
    const int b_r = (lane & 7) + ((lane >> 4) << 3);
    const int b_c = ((lane >> 3) & 1) * 8;
#pragma unroll
    for (int ks = 0; ks < 8; ks++) {
        const int k0 = ks * 16;
        uint32_t ah[2][4], al[2][4];
#pragma unroll
        for (int mt = 0; mt < 2; mt++) {
            uint32_t off = (uint32_t)((wm * 32 + mt * 16 + a_r) * ASTRIDE + k0 + a_c) * 2;
            ldsm4(ah[mt][0], ah[mt][1], ah[mt][2], ah[mt][3], ah_base + off);
            ldsm4(al[mt][0], al[mt][1], al[mt][2], al[mt][3], al_base + off);
        }
        uint32_t bh[8][2];
#pragma unroll
        for (int ng = 0; ng < 4; ng++) {
            uint32_t off = (uint32_t)((wn * 64 + ng * 16 + b_r) * ASTRIDE + k0 + b_c) * 2;
            ldsm4(bh[2 * ng][0], bh[2 * ng][1], bh[2 * ng + 1][0], bh[2 * ng + 1][1], bh_base + off);
        }
#pragma unroll
        for (int mt = 0; mt < 2; mt++)
#pragma unroll
            for (int nt = 0; nt < 8; nt++) {
                mma_f16(acc[mt][nt], ah[mt], bh[nt]);
                mma_f16(acc[mt][nt], al[mt], bh[nt]);
            }
    }
}

// ---------------- CSR build ----------------
__global__ void zero_k() {
    int i = blockIdx.x * blockDim.x + threadIdx.x;
    if (i < NN) g_cursor[i] = 0;
}
__global__ void hist_k(const int* __restrict__ dst) {
    int e = blockIdx.x * blockDim.x + threadIdx.x;
    if (e < EE) atomicAdd(&g_cursor[dst[e]], 1);
}
__global__ __launch_bounds__(1024) void scan_k() {
    __shared__ int warpsum[32];
    __shared__ int s_carry;
    __shared__ int s_tot;
    int tid = threadIdx.x, lane = tid & 31, wid = tid >> 5;
    if (tid == 0) s_carry = 0;
    __syncthreads();
    for (int base = 0; base < NN; base += 8192) {
        int idx0 = base + tid * 8;
        int v[8]; int tot = 0;
#pragma unroll
        for (int j = 0; j < 8; j++) {
            int id = idx0 + j;
            v[j] = (id < NN) ? g_cursor[id] : 0;
            tot += v[j];
        }
        int incl = tot;
#pragma unroll
        for (int off = 1; off < 32; off <<= 1) {
            int t = __shfl_up_sync(0xffffffffu, incl, off);
            if (lane >= off) incl += t;
        }
        if (lane == 31) warpsum[wid] = incl;
        __syncthreads();
        if (wid == 0) {
            int w = warpsum[lane];
            int wi = w;
#pragma unroll
            for (int off = 1; off < 32; off <<= 1) {
                int t = __shfl_up_sync(0xffffffffu, wi, off);
                if (lane >= off) wi += t;
            }
            warpsum[lane] = wi - w;
            if (lane == 31) s_tot = wi;
        }
        __syncthreads();
        int run = s_carry + warpsum[wid] + (incl - tot);
#pragma unroll
        for (int j = 0; j < 8; j++) {
            int id = idx0 + j;
            if (id < NN) { g_rowptr[id] = run; g_cursor[id] = 0; }
            run += v[j];
        }
        __syncthreads();
        if (tid == 0) s_carry += s_tot;
        __syncthreads();
    }
    if (threadIdx.x == 0) g_rowptr[NN] = s_carry;
}
__global__ void scatter_k(const int* __restrict__ src, const int* __restrict__ dst) {
    int e = blockIdx.x * blockDim.x + threadIdx.x;
    if (e < EE) {
        int d = dst[e];
        int pos = g_rowptr[d] + atomicAdd(&g_cursor[d], 1);
        g_esrc[pos] = src[e];
    }
}

// ---------------- conversions ----------------
__global__ void convw_k(const float* __restrict__ Wa, const float* __restrict__ Wb,
                        const float* __restrict__ ba, const float* __restrict__ bb,
                        __half* __restrict__ Wt, float* __restrict__ bc, int na, int nb) {
    int nc = na + nb;
    int i = blockIdx.x * blockDim.x + threadIdx.x;
    if (i < nc * 128) {
        int n = i >> 7, k = i & 127;
        float v = (n < na) ? Wa[(size_t)k * na + n] : Wb[(size_t)k * nb + (n - na)];
        Wt[i] = __float2half_rn(v);
    }
    if (bc && i < nc) bc[i] = (i < na) ? ba[i] : bb[i - na];
}

// merged main-chain conversion: w0t (128x128) + wqp1t (256x128) + bqp1
__global__ void convw_l1_k(const float* __restrict__ W0,
                           const float* __restrict__ Wq1, const float* __restrict__ Wp1,
                           const float* __restrict__ bq1, const float* __restrict__ bp1) {
    int i = blockIdx.x * blockDim.x + threadIdx.x;
    if (i < 128 * 128) {
        int n = i >> 7, k = i & 127;
        g_w0t[i] = __float2half_rn(W0[(size_t)k * 128 + n]);
    } else if (i < 128 * 128 + 256 * 128) {
        int j = i - 128 * 128;
        int n = j >> 7, k = j & 127;
        float v = (n < 128) ? Wq1[(size_t)k * 128 + n] : Wp1[(size_t)k * 128 + (n - 128)];
        g_wqp1t[j] = __float2half_rn(v);
    }
    if (i < 256) g_bqp1[i] = (i < 128) ? bq1[i] : bp1[i - 128];
}

// ---------------- fused layer-1: qp1 = gelu(x@W0+b0) @ Wqp1 + bqp1 (fp32 out) --
__global__ __launch_bounds__(256, 2) void gemm_l1(
    const float* __restrict__ x, const __half* __restrict__ W0t,
    const float* __restrict__ b0, const __half* __restrict__ Wqp1t,
    const float* __restrict__ bqp1, float* __restrict__ qp1, int M)
{
    extern __shared__ char sm[];
    char* AH = sm;
    char* AL = sm + ABUF;
    char* BH = sm + 2 * ABUF;

    const int tid = threadIdx.x;
    const int warp = tid >> 5, lane = tid & 31;
    const int wm = warp >> 1, wn = warp & 1;
    const int rowBase = blockIdx.x * 128;

    const uint32_t ah_base = smem_u32(AH);
    const uint32_t al_base = smem_u32(AL);
    const uint32_t bh_base = smem_u32(BH);

    // ---- stage W0 (async) + x (fp32 -> hi/lo in regs) ----
#pragma unroll
    for (int it = 0; it < 8; it++) {
        int idx = tid + it * 256;
        int row = idx >> 4, ch = idx & 15;
        uint32_t so = (uint32_t)(row * ASTRIDE + ch * 8) * 2;
        cp16(bh_base + so, W0t + (size_t)row * 128 + ch * 8);
    }
    asm volatile("cp.async.commit_group;" ::: "memory");
#pragma unroll
    for (int it = 0; it < 8; it++) {
        int idx = tid + it * 256;
        int row = idx >> 4, ch = idx & 15;
        int gr = rowBase + row; if (gr >= M) gr = M - 1;
        float4 v0 = *(const float4*)(x + (size_t)gr * 128 + ch * 8);
        float4 v1 = *(const float4*)(x + (size_t)gr * 128 + ch * 8 + 4);
        __half hh[8], ll[8];
        split_h(v0.x, hh[0], ll[0]); split_h(v0.y, hh[1], ll[1]);
        split_h(v0.z, hh[2], ll[2]); split_h(v0.w, hh[3], ll[3]);
        split_h(v1.x, hh[4], ll[4]); split_h(v1.y, hh[5], ll[5]);
        split_h(v1.z, hh[6], ll[6]); split_h(v1.w, hh[7], ll[7]);
        uint32_t so = (uint32_t)(row * ASTRIDE + ch * 8) * 2;
        *(uint4*)(AH + so) = *(const uint4*)hh;
        *(uint4*)(AL + so) = *(const uint4*)ll;
    }
    asm volatile("cp.async.wait_group 0;" ::: "memory");
    __syncthreads();

    float acc[2][8][4];
#pragma unroll
    for (int i = 0; i < 2; i++)
#pragma unroll
        for (int j = 0; j < 8; j++)
#pragma unroll
            for (int k = 0; k < 4; k++) acc[i][j][k] = 0.f;

    // ---- mainloop 1: m1 = x @ W0^T ----
    mainloop_f16(ah_base, al_base, bh_base, wm, wn, lane, acc);
    __syncthreads();   // all warps done reading AH/AL/BH

    // ---- prefetch Wqp1 col-half 0, overlapped with epilogue-1 ----
#pragma unroll
    for (int it = 0; it < 8; it++) {
        int idx = tid + it * 256;
        int row = idx >> 4, ch = idx & 15;
        uint32_t so = (uint32_t)(row * ASTRIDE + ch * 8) * 2;
        cp16(bh_base + so, Wqp1t + (size_t)row * 128 + ch * 8);
    }
    asm volatile("cp.async.commit_group;" ::: "memory");

    // ---- epilogue 1: gelu(m1+b0), split, write back into AH/AL ----
#pragma unroll
    for (int mt = 0; mt < 2; mt++)
#pragma unroll
        for (int nt = 0; nt < 8; nt++) {
            int c = wn * 64 + nt * 8 + (lane & 3) * 2;
            float bb0 = b0[c], bb1 = b0[c + 1];
#pragma unroll
            for (int h = 0; h < 2; h++) {
                int r = wm * 32 + mt * 16 + (lane >> 2) + h * 8;
                float v0 = gelu_f(acc[mt][nt][2 * h + 0] + bb0);
                float v1 = gelu_f(acc[mt][nt][2 * h + 1] + bb1);
                __half h0, l0, h1, l1;
                split_h(v0, h0, l0);
                split_h(v1, h1, l1);
                uint32_t so = (uint32_t)(r * ASTRIDE + c) * 2;
                __half2 hh; hh.x = h0; hh.y = h1;
                __half2 ll; ll.x = l0; ll.y = l1;
                *(__half2*)(AH + so) = hh;
                *(__half2*)(AL + so) = ll;
            }
        }
    asm volatile("cp.async.wait_group 0;" ::: "memory");
    __syncthreads();

    // ---- stage 2: two column-halves of qp1 = m1 @ Wqp1^T ----
#pragma unroll
    for (int cb = 0; cb < 2; cb++) {
#pragma unroll
        for (int i = 0; i < 2; i++)
#pragma unroll
            for (int j = 0; j < 8; j++)
#pragma unroll
                for (int k = 0; k < 4; k++) acc[i][j][k] = 0.f;
        mainloop_f16(ah_base, al_base, bh_base, wm, wn, lane, acc);

        if (cb == 0) {
            __syncthreads();   // done reading BH; restage with col-half 1
#pragma unroll
            for (int it = 0; it < 8; it++) {
                int idx = tid + it * 256;
                int row = idx >> 4, ch = idx & 15;
                uint32_t so = (uint32_t)(row * ASTRIDE + ch * 8) * 2;
                cp16(bh_base + so, Wqp1t + (size_t)(128 + row) * 128 + ch * 8);
            }
            asm volatile("cp.async.commit_group;" ::: "memory");
        }

#pragma unroll
        for (int mt = 0; mt < 2; mt++)
#pragma unroll
            for (int nt = 0; nt < 8; nt++) {
                int c = cb * 128 + wn * 64 + nt * 8 + (lane & 3) * 2;
                float bb0 = bqp1[c], bb1 = bqp1[c + 1];
#pragma unroll
                for (int h = 0; h < 2; h++) {
                    int r = rowBase + wm * 32 + mt * 16 + (lane >> 2) + h * 8;
                    if (r < M) {
                        float v0 = acc[mt][nt][2 * h + 0] + bb0;
                        float v1 = acc[mt][nt][2 * h + 1] + bb1;
                        *(float2*)(qp1 + (size_t)r * 256 + c) = make_float2(v0, v1);
                    }
                }
            }
        if (cb == 0) {
            asm volatile("cp.async.wait_group 0;" ::: "memory");
            __syncthreads();
        }
    }
}

// ---------------- layer-2 GEMM (reads m2 hi/lo, writes fp32 qp2) -------------
__global__ __launch_bounds__(256, 2) void gemm_mma(
    const __half* __restrict__ Ahi, const __half* __restrict__ Alo,
    const __half* __restrict__ Bh, const float* __restrict__ bias,
    float* __restrict__ Cf, int M, int ncols)
{
    extern __shared__ char sm[];
    char* AH = sm;
    char* AL = sm + ABUF;
    char* BH = sm + 2 * ABUF;

    const int tid = threadIdx.x;
    const int warp = tid >> 5, lane = tid & 31;
    const int wm = warp >> 1, wn = warp & 1;
    const int rowBase = blockIdx.x * 128;

    const uint32_t ah_base = smem_u32(AH);
    const uint32_t al_base = smem_u32(AL);
    const uint32_t bh_base = smem_u32(BH);

#pragma unroll
    for (int it = 0; it < 8; it++) {
        int idx = tid + it * 256;
        int row = idx >> 4, ch = idx & 15;
        int gr = rowBase + row; if (gr >= M) gr = M - 1;
        uint32_t so = (uint32_t)(row * ASTRIDE + ch * 8) * 2;
        cp16(ah_base + so, Ahi + (size_t)gr * 128 + ch * 8);
        cp16(al_base + so, Alo + (size_t)gr * 128 + ch * 8);
        cp16(bh_base + so, Bh + (size_t)row * 128 + ch * 8);
    }
    asm volatile("cp.async.commit_group;" ::: "memory");
    asm volatile("cp.async.wait_group 0;" ::: "memory");
    __syncthreads();

    float acc[2][8][4];
#pragma unroll
    for (int i = 0; i < 2; i++)
#pragma unroll
        for (int j = 0; j < 8; j++)
#pragma unroll
            for (int k = 0; k < 4; k++) acc[i][j][k] = 0.f;
    mainloop_f16(ah_base, al_base, bh_base, wm, wn, lane, acc);

#pragma unroll
    for (int mt = 0; mt < 2; mt++)
#pragma unroll
        for (int nt = 0; nt < 8; nt++) {
            int c = wn * 64 + nt * 8 + (lane & 3) * 2;
            float b0 = bias[c], b1 = bias[c + 1];
#pragma unroll
            for (int h = 0; h < 2; h++) {
                int r = rowBase + wm * 32 + mt * 16 + (lane >> 2) + h * 8;
                if (r < M) {
                    float v0 = acc[mt][nt][2 * h + 0] + b0;
                    float v1 = acc[mt][nt][2 * h + 1] + b1;
                    *(float2*)(Cf + (size_t)r * ncols + c) = make_float2(v0, v1);
                }
            }
        }
}

// ---------------- edge kernels: one warp per dst node (R8 formulation) --------
__global__ __launch_bounds__(256) void edge128_k(
    const float* __restrict__ qp, const float* __restrict__ a,
    const float* __restrict__ bg)
{
    int gw = (blockIdx.x * 256 + threadIdx.x) >> 5;
    if (gw >= NN) return;
    int lane = threadIdx.x & 31;
    int c = lane * 4;
    float4 qv = *(const float4*)(qp + (size_t)gw * 256 + c);
    float4 av = *(const float4*)(a + c);
    float ax = 0.f, ay = 0.f, az = 0.f, aw = 0.f;
    float denom = 0.f;
    int i = g_rowptr[gw];
    int end = g_rowptr[gw + 1];
    if (i < end) {
        int s = g_esrc[i];
        float4 pv = *(const float4*)(qp + (size_t)s * 256 + 128 + c);
        while (1) {
            float4 pvn;
            if (i + 1 < end) {
                int sn = g_esrc[i + 1];
                pvn = *(const float4*)(qp + (size_t)sn * 256 + 128 + c);
            }
            float tx = qv.x + pv.x; tx = tx > 0.f ? tx : 0.2f * tx;
            float ty = qv.y + pv.y; ty = ty > 0.f ? ty : 0.2f * ty;
            float tz = qv.z + pv.z; tz = tz > 0.f ? tz : 0.2f * tz;
            float tw = qv.w + pv.w; tw = tw > 0.f ? tw : 0.2f * tw;
            float part = fmaf(tx, av.x, fmaf(ty, av.y, fmaf(tz, av.z, tw * av.w)));
#pragma unroll
            for (int off = 16; off > 0; off >>= 1)
                part += __shfl_xor_sync(0xffffffffu, part, off);
            float es = __expf(part);
            denom += es;
            ax = fmaf(es, pv.x, ax);
            ay = fmaf(es, pv.y, ay);
            az = fmaf(es, pv.z, az);
            aw = fmaf(es, pv.w, aw);
            i++;
            if (i >= end) break;
            pv = pvn;
        }
    }
    float inv = denom > 0.f ? 1.0f / denom : 0.f;
    float4 bv = *(const float4*)(bg + c);
    float o[4];
    o[0] = gelu_f(fmaf(ax, inv, bv.x));
    o[1] = gelu_f(fmaf(ay, inv, bv.y));
    o[2] = gelu_f(fmaf(az, inv, bv.z));
    o[3] = gelu_f(fmaf(aw, inv, bv.w));
    __half h[4], l[4];
#pragma unroll
    for (int j = 0; j < 4; j++) split_h(o[j], h[j], l[j]);
    __half2 hh0; hh0.x = h[0]; hh0.y = h[1];
    __half2 hh1; hh1.x = h[2]; hh1.y = h[3];
    __half2 ll0; ll0.x = l[0]; ll0.y = l[1];
    __half2 ll1; ll1.x = l[2]; ll1.y = l[3];
    *(__half2*)(g_m2hi + (size_t)gw * 128 + c) = hh0;
    *(__half2*)(g_m2hi + (size_t)gw * 128 + c + 2) = hh1;
    *(__half2*)(g_m2lo + (size_t)gw * 128 + c) = ll0;
    *(__half2*)(g_m2lo + (size_t)gw * 128 + c + 2) = ll1;
}

__global__ __launch_bounds__(256) void edge64_k(
    const float* __restrict__ qp, const float* __restrict__ a,
    const float* __restrict__ bo, float* __restrict__ out)
{
    int gw = (blockIdx.x * 256 + threadIdx.x) >> 5;
    if (gw >= NN) return;
    int lane = threadIdx.x & 31;
    int c = lane * 2;
    float2 qv = *(const float2*)(qp + (size_t)gw * 128 + c);
    float2 av = *(const float2*)(a + c);
    float ax = 0.f, ay = 0.f;
    float denom = 0.f;
    int i = g_rowptr[gw];
    int end = g_rowptr[gw + 1];
    if (i < end) {
        int s = g_esrc[i];
        float2 pv = *(const float2*)(qp + (size_t)s * 128 + 64 + c);
        while (1) {
            float2 pvn;
            if (i + 1 < end) {
                int sn = g_esrc[i + 1];
                pvn = *(const float2*)(qp + (size_t)sn * 128 + 64 + c);
            }
            float tx = qv.x + pv.x; tx = tx > 0.f ? tx : 0.2f * tx;
            float ty = qv.y + pv.y; ty = ty > 0.f ? ty : 0.2f * ty;
            float part = fmaf(tx, av.x, ty * av.y);
#pragma unroll
            for (int off = 16; off > 0; off >>= 1)
                part += __shfl_xor_sync(0xffffffffu, part, off);
            float es = __expf(part);
            denom += es;
            ax = fmaf(es, pv.x, ax);
            ay = fmaf(es, pv.y, ay);
            i++;
            if (i >= end) break;
            pv = pvn;
        }
    }
    float inv = denom > 0.f ? 1.0f / denom : 0.f;
    float2 bv = *(const float2*)(bo + c);
    float2 o;
    o.x = fmaf(ax, inv, bv.x);
    o.y = fmaf(ay, inv, bv.y);
    *(float2*)(out + (size_t)gw * 64 + c) = o;
}

// ---------------- launch ----------------
extern "C" void kernel_launch(void* const* d_in, const int* in_sizes, int n_in,
                              void* d_out, int out_size)
{
    const float* x    = (const float*)d_in[0];
    const float* W0   = (const float*)d_in[1];
    const float* b0   = (const float*)d_in[2];
    const float* Wq1  = (const float*)d_in[3];
    const float* bq1  = (const float*)d_in[4];
    const float* Wp1  = (const float*)d_in[5];
    const float* bp1  = (const float*)d_in[6];
    const float* a1   = (const float*)d_in[7];
    const float* bg2  = (const float*)d_in[8];
    const float* Wq2  = (const float*)d_in[9];
    const float* bq2  = (const float*)d_in[10];
    const float* Wp2  = (const float*)d_in[11];
    const float* bp2  = (const float*)d_in[12];
    const float* a2   = (const float*)d_in[13];
    const float* bout = (const float*)d_in[14];
    const int*   src  = (const int*)d_in[15];
    const int*   dst  = (const int*)d_in[16];
    float* out = (float*)d_out;

    __half *m2hi, *m2lo, *w0t, *wqp1t, *wqp2t;
    float *qp1, *qp2, *bqp1, *bqp2;
    cudaGetSymbolAddress((void**)&m2hi, g_m2hi); cudaGetSymbolAddress((void**)&m2lo, g_m2lo);
    cudaGetSymbolAddress((void**)&w0t, g_w0t);
    cudaGetSymbolAddress((void**)&wqp1t, g_wqp1t);
    cudaGetSymbolAddress((void**)&wqp2t, g_wqp2t);
    cudaGetSymbolAddress((void**)&qp1, g_qp1); cudaGetSymbolAddress((void**)&qp2, g_qp2);
    cudaGetSymbolAddress((void**)&bqp1, g_bqp1); cudaGetSymbolAddress((void**)&bqp2, g_bqp2);

    constexpr int SMEM = 3 * ABUF;   // 104448 B
    cudaFuncSetAttribute(gemm_l1, cudaFuncAttributeMaxDynamicSharedMemorySize, SMEM);
    cudaFuncSetAttribute(gemm_mma, cudaFuncAttributeMaxDynamicSharedMemorySize, SMEM);

    // ---- fork: CSR build + layer-2 weight conversion on side stream ----
    cudaStream_t s2;
    cudaStreamCreateWithFlags(&s2, cudaStreamNonBlocking);
    cudaEvent_t evFork, evJoin;
    cudaEventCreateWithFlags(&evFork, cudaEventDisableTiming);
    cudaEventCreateWithFlags(&evJoin, cudaEventDisableTiming);

    cudaEventRecord(evFork, 0);
    cudaStreamWaitEvent(s2, evFork, 0);
    zero_k<<<(NN + 255) / 256, 256, 0, s2>>>();
    hist_k<<<(EE + 255) / 256, 256, 0, s2>>>(dst);
    scan_k<<<1, 1024, 0, s2>>>();
    scatter_k<<<(EE + 255) / 256, 256, 0, s2>>>(src, dst);
    convw_k<<<(128 * 128 + 255) / 256, 256, 0, s2>>>(Wq2, Wp2, bq2, bp2, wqp2t, bqp2, 64, 64);
    cudaEventRecord(evJoin, s2);

    // ---- main chain: merged layer-1 weight conversion, then fused layer-1 ----
    convw_l1_k<<<(128 * 128 + 256 * 128 + 255) / 256, 256>>>(W0, Wq1, Wp1, bq1, bp1);

    const int MB = (NN + 127) / 128;

    gemm_l1<<<MB, 256, SMEM>>>(x, w0t, b0, wqp1t, bqp1, qp1, NN);

    cudaStreamWaitEvent(0, evJoin, 0);
    edge128_k<<<(NN * 32 + 255) / 256, 256>>>(qp1, a1, bg2);       // m2 (fp16 hi/lo)

    gemm_mma<<<MB, 256, SMEM>>>(m2hi, m2lo, wqp2t, bqp2, qp2, NN, 128);
    edge64_k<<<(NN * 32 + 255) / 256, 256>>>(qp2, a2, bout, out);
}

// round 12
// speedup vs baseline: 1.1236x; 1.0973x over previous
#include <cuda_runtime.h>
#include <cuda_fp16.h>
#include <cstdint>

#define NN 50000
#define EE 800000
#define NSPLIT 25088   // 196 * 128

// ---------------- scratch (static device globals; no allocs) ----------------
__device__ __half g_m2hi[NN * 128], g_m2lo[NN * 128];
__device__ float g_qp1[NN * 256];   // [node][0:128]=q1, [128:256]=p1
__device__ float g_qp2[NN * 128];   // [node][0:64]=q2, [64:128]=p2
__device__ __half g_w0t[128 * 128];
__device__ __half g_wqp1t[256 * 128];
__device__ __half g_wqp2t[128 * 128];
__device__ float g_bqp1[256];
__device__ float g_bqp2[128];
__device__ int   g_rowptr[NN + 1];
__device__ int   g_cursor[NN];
__device__ int   g_esrc[EE];

__device__ __forceinline__ float gelu_f(float x) {
    return 0.5f * x * (1.0f + erff(x * 0.70710678118654752440f));
}
__device__ __forceinline__ void split_h(float v, __half& hi, __half& lo) {
    hi = __float2half_rn(v);
    lo = __float2half_rn(v - __half2float(hi));
}
__device__ __forceinline__ uint32_t smem_u32(const void* p) {
    uint32_t a;
    asm("{ .reg .u64 t; cvta.to.shared.u64 t, %1; cvt.u32.u64 %0, t; }" : "=r"(a) : "l"(p));
    return a;
}
__device__ __forceinline__ void ldsm4(uint32_t& r0, uint32_t& r1, uint32_t& r2, uint32_t& r3, uint32_t addr) {
    asm volatile("ldmatrix.sync.aligned.m8n8.x4.shared.b16 {%0,%1,%2,%3}, [%4];"
                 : "=r"(r0), "=r"(r1), "=r"(r2), "=r"(r3) : "r"(addr));
}
__device__ __forceinline__ void mma_f16(float* c, const uint32_t* a, const uint32_t* b) {
    asm volatile(
        "mma.sync.aligned.m16n8k16.row.col.f32.f16.f16.f32 "
        "{%0,%1,%2,%3}, {%4,%5,%6,%7}, {%8,%9}, {%0,%1,%2,%3};"
        : "+f"(c[0]), "+f"(c[1]), "+f"(c[2]), "+f"(c[3])
        : "r"(a[0]), "r"(a[1]), "r"(a[2]), "r"(a[3]), "r"(b[0]), "r"(b[1]));
}
__device__ __forceinline__ void cp16(uint32_t saddr, const void* gaddr) {
    asm volatile("cp.async.cg.shared.global [%0], [%1], 16;" :: "r"(saddr), "l"(gaddr) : "memory");
}

#define ASTRIDE 136
#define ABUF (128 * ASTRIDE * 2)   // 34816 B per buffer

__device__ __forceinline__ void mainloop_f16(
    uint32_t ah_base, uint32_t al_base, uint32_t bh_base,
    int wm, int wn, int lane, float acc[2][8][4])
{
    const int a_r = (lane & 15);
    const int a_c = (lane >> 4) * 8;
    const int b_r = (lane & 7) + ((lane >> 4) << 3);
    const int b_c = ((lane >> 3) & 1) * 8;
#pragma unroll
    for (int ks = 0; ks < 8; ks++) {
        const int k0 = ks * 16;
        uint32_t ah[2][4], al[2][4];
#pragma unroll
        for (int mt = 0; mt < 2; mt++) {
            uint32_t off = (uint32_t)((wm * 32 + mt * 16 + a_r) * ASTRIDE + k0 + a_c) * 2;
            ldsm4(ah[mt][0], ah[mt][1], ah[mt][2], ah[mt][3], ah_base + off);
            ldsm4(al[mt][0], al[mt][1], al[mt][2], al[mt][3], al_base + off);
        }
        uint32_t bh[8][2];
#pragma unroll
        for (int ng = 0; ng < 4; ng++) {
            uint32_t off = (uint32_t)((wn * 64 + ng * 16 + b_r) * ASTRIDE + k0 + b_c) * 2;
            ldsm4(bh[2 * ng][0], bh[2 * ng][1], bh[2 * ng + 1][0], bh[2 * ng + 1][1], bh_base + off);
        }
#pragma unroll
        for (int mt = 0; mt < 2; mt++)
#pragma unroll
            for (int nt = 0; nt < 8; nt++) {
                mma_f16(acc[mt][nt], ah[mt], bh[nt]);
                mma_f16(acc[mt][nt], al[mt], bh[nt]);
            }
    }
}

// ---------------- CSR build ----------------
__global__ void zero_k() {
    int i = blockIdx.x * blockDim.x + threadIdx.x;
    if (i < NN) g_cursor[i] = 0;
}
__global__ void hist_k(const int* __restrict__ dst) {
    int e = blockIdx.x * blockDim.x + threadIdx.x;
    if (e < EE) atomicAdd(&g_cursor[dst[e]], 1);
}
__global__ __launch_bounds__(1024) void scan_k() {
    __shared__ int warpsum[32];
    __shared__ int s_carry;
    __shared__ int s_tot;
    int tid = threadIdx.x, lane = tid & 31, wid = tid >> 5;
    if (tid == 0) s_carry = 0;
    __syncthreads();
    for (int base = 0; base < NN; base += 8192) {
        int idx0 = base + tid * 8;
        int v[8]; int tot = 0;
#pragma unroll
        for (int j = 0; j < 8; j++) {
            int id = idx0 + j;
            v[j] = (id < NN) ? g_cursor[id] : 0;
            tot += v[j];
        }
        int incl = tot;
#pragma unroll
        for (int off = 1; off < 32; off <<= 1) {
            int t = __shfl_up_sync(0xffffffffu, incl, off);
            if (lane >= off) incl += t;
        }
        if (lane == 31) warpsum[wid] = incl;
        __syncthreads();
        if (wid == 0) {
            int w = warpsum[lane];
            int wi = w;
#pragma unroll
            for (int off = 1; off < 32; off <<= 1) {
                int t = __shfl_up_sync(0xffffffffu, wi, off);
                if (lane >= off) wi += t;
            }
            warpsum[lane] = wi - w;
            if (lane == 31) s_tot = wi;
        }
        __syncthreads();
        int run = s_carry + warpsum[wid] + (incl - tot);
#pragma unroll
        for (int j = 0; j < 8; j++) {
            int id = idx0 + j;
            if (id < NN) { g_rowptr[id] = run; g_cursor[id] = 0; }
            run += v[j];
        }
        __syncthreads();
        if (tid == 0) s_carry += s_tot;
        __syncthreads();
    }
    if (threadIdx.x == 0) g_rowptr[NN] = s_carry;
}
__global__ void scatter_k(const int* __restrict__ src, const int* __restrict__ dst) {
    int e = blockIdx.x * blockDim.x + threadIdx.x;
    if (e < EE) {
        int d = dst[e];
        int pos = g_rowptr[d] + atomicAdd(&g_cursor[d], 1);
        g_esrc[pos] = src[e];
    }
}

// ---------------- conversions ----------------
__global__ void convw_k(const float* __restrict__ Wa, const float* __restrict__ Wb,
                        const float* __restrict__ ba, const float* __restrict__ bb,
                        __half* __restrict__ Wt, float* __restrict__ bc, int na, int nb) {
    int nc = na + nb;
    int i = blockIdx.x * blockDim.x + threadIdx.x;
    if (i < nc * 128) {
        int n = i >> 7, k = i & 127;
        float v = (n < na) ? Wa[(size_t)k * na + n] : Wb[(size_t)k * nb + (n - na)];
        Wt[i] = __float2half_rn(v);
    }
    if (bc && i < nc) bc[i] = (i < na) ? ba[i] : bb[i - na];
}

// ---------------- fused layer-1 (byte-exact R8): qp1 = gelu(x@W0+b0) @ Wqp1 --
__global__ __launch_bounds__(256, 2) void gemm_l1(
    const float* __restrict__ x, const __half* __restrict__ W0t,
    const float* __restrict__ b0, const __half* __restrict__ Wqp1t,
    const float* __restrict__ bqp1, float* __restrict__ qp1, int M)
{
    extern __shared__ char sm[];
    char* AH = sm;
    char* AL = sm + ABUF;
    char* BH = sm + 2 * ABUF;

    const int tid = threadIdx.x;
    const int warp = tid >> 5, lane = tid & 31;
    const int wm = warp >> 1, wn = warp & 1;
    const int rowBase = blockIdx.x * 128;

    const uint32_t ah_base = smem_u32(AH);
    const uint32_t al_base = smem_u32(AL);
    const uint32_t bh_base = smem_u32(BH);

    // ---- W0 via cp.async; x staged with in-register fp32->hi/lo conversion ----
#pragma unroll
    for (int it = 0; it < 8; it++) {
        int idx = tid + it * 256;               // 0..2047
        int row = idx >> 4, ch = idx & 15;
        uint32_t so = (uint32_t)(row * ASTRIDE + ch * 8) * 2;
        cp16(bh_base + so, W0t + (size_t)row * 128 + ch * 8);
    }
    asm volatile("cp.async.commit_group;" ::: "memory");
#pragma unroll
    for (int it = 0; it < 8; it++) {
        int idx = tid + it * 256;
        int row = idx >> 4, ch = idx & 15;
        int gr = rowBase + row; if (gr >= M) gr = M - 1;
        float4 v0 = *(const float4*)(x + (size_t)gr * 128 + ch * 8);
        float4 v1 = *(const float4*)(x + (size_t)gr * 128 + ch * 8 + 4);
        __half hh[8], ll[8];
        split_h(v0.x, hh[0], ll[0]); split_h(v0.y, hh[1], ll[1]);
        split_h(v0.z, hh[2], ll[2]); split_h(v0.w, hh[3], ll[3]);
        split_h(v1.x, hh[4], ll[4]); split_h(v1.y, hh[5], ll[5]);
        split_h(v1.z, hh[6], ll[6]); split_h(v1.w, hh[7], ll[7]);
        uint32_t so = (uint32_t)(row * ASTRIDE + ch * 8) * 2;
        *(uint4*)(AH + so) = *(const uint4*)hh;
        *(uint4*)(AL + so) = *(const uint4*)ll;
    }
    asm volatile("cp.async.wait_group 0;" ::: "memory");
    __syncthreads();

    float acc[2][8][4];
#pragma unroll
    for (int i = 0; i < 2; i++)
#pragma unroll
        for (int j = 0; j < 8; j++)
#pragma unroll
            for (int k = 0; k < 4; k++) acc[i][j][k] = 0.f;

    // ---- mainloop 1: m1 = x @ W0^T ----
    mainloop_f16(ah_base, al_base, bh_base, wm, wn, lane, acc);
    __syncthreads();   // everyone done reading AH/AL

    // ---- epilogue 1: gelu(m1+b0), split, write back into AH/AL ----
#pragma unroll
    for (int mt = 0; mt < 2; mt++)
#pragma unroll
        for (int nt = 0; nt < 8; nt++) {
            int c = wn * 64 + nt * 8 + (lane & 3) * 2;
            float bb0 = b0[c], bb1 = b0[c + 1];
#pragma unroll
            for (int h = 0; h < 2; h++) {
                int r = wm * 32 + mt * 16 + (lane >> 2) + h * 8;
                float v0 = gelu_f(acc[mt][nt][2 * h + 0] + bb0);
                float v1 = gelu_f(acc[mt][nt][2 * h + 1] + bb1);
                __half h0, l0, h1, l1;
                split_h(v0, h0, l0);
                split_h(v1, h1, l1);
                uint32_t so = (uint32_t)(r * ASTRIDE + c) * 2;
                __half2 hh; hh.x = h0; hh.y = h1;
                __half2 ll; ll.x = l0; ll.y = l1;
                *(__half2*)(AH + so) = hh;
                *(__half2*)(AL + so) = ll;
            }
        }
    __syncthreads();

    // ---- stage 2: two column-halves of qp1 = m1 @ Wqp1^T ----
#pragma unroll
    for (int cb = 0; cb < 2; cb++) {
#pragma unroll
        for (int it = 0; it < 8; it++) {
            int idx = tid + it * 256;
            int row = idx >> 4, ch = idx & 15;
            uint32_t so = (uint32_t)(row * ASTRIDE + ch * 8) * 2;
            cp16(bh_base + so, Wqp1t + (size_t)(cb * 128 + row) * 128 + ch * 8);
        }
        asm volatile("cp.async.commit_group;" ::: "memory");
        asm volatile("cp.async.wait_group 0;" ::: "memory");
        __syncthreads();

#pragma unroll
        for (int i = 0; i < 2; i++)
#pragma unroll
            for (int j = 0; j < 8; j++)
#pragma unroll
                for (int k = 0; k < 4; k++) acc[i][j][k] = 0.f;
        mainloop_f16(ah_base, al_base, bh_base, wm, wn, lane, acc);

#pragma unroll
        for (int mt = 0; mt < 2; mt++)
#pragma unroll
            for (int nt = 0; nt < 8; nt++) {
                int c = cb * 128 + wn * 64 + nt * 8 + (lane & 3) * 2;
                float bb0 = bqp1[c], bb1 = bqp1[c + 1];
#pragma unroll
                for (int h = 0; h < 2; h++) {
                    int r = rowBase + wm * 32 + mt * 16 + (lane >> 2) + h * 8;
                    if (r < M) {
                        float v0 = acc[mt][nt][2 * h + 0] + bb0;
                        float v1 = acc[mt][nt][2 * h + 1] + bb1;
                        *(float2*)(qp1 + (size_t)r * 256 + c) = make_float2(v0, v1);
                    }
                }
            }
        if (cb == 0) __syncthreads();   // before overwriting BH
    }
}

// ---------------- layer-2 GEMM (byte-exact R8 + rowOffset) -------------------
__global__ __launch_bounds__(256, 2) void gemm_mma(
    const __half* __restrict__ Ahi, const __half* __restrict__ Alo,
    const __half* __restrict__ Bh, const float* __restrict__ bias,
    float* __restrict__ Cf, int M, int ncols, int rowOffset)
{
    extern __shared__ char sm[];
    char* AH = sm;
    char* AL = sm + ABUF;
    char* BH = sm + 2 * ABUF;

    const int tid = threadIdx.x;
    const int warp = tid >> 5, lane = tid & 31;
    const int wm = warp >> 1, wn = warp & 1;
    const int rowBase = rowOffset + blockIdx.x * 128;

    const uint32_t ah_base = smem_u32(AH);
    const uint32_t al_base = smem_u32(AL);
    const uint32_t bh_base = smem_u32(BH);

#pragma unroll
    for (int it = 0; it < 8; it++) {
        int idx = tid + it * 256;
        int row = idx >> 4, ch = idx & 15;
        int gr = rowBase + row; if (gr >= M) gr = M - 1;
        uint32_t so = (uint32_t)(row * ASTRIDE + ch * 8) * 2;
        cp16(ah_base + so, Ahi + (size_t)gr * 128 + ch * 8);
        cp16(al_base + so, Alo + (size_t)gr * 128 + ch * 8);
        cp16(bh_base + so, Bh + (size_t)row * 128 + ch * 8);
    }
    asm volatile("cp.async.commit_group;" ::: "memory");
    asm volatile("cp.async.wait_group 0;" ::: "memory");
    __syncthreads();

    float acc[2][8][4];
#pragma unroll
    for (int i = 0; i < 2; i++)
#pragma unroll
        for (int j = 0; j < 8; j++)
#pragma unroll
            for (int k = 0; k < 4; k++) acc[i][j][k] = 0.f;
    mainloop_f16(ah_base, al_base, bh_base, wm, wn, lane, acc);

#pragma unroll
    for (int mt = 0; mt < 2; mt++)
#pragma unroll
        for (int nt = 0; nt < 8; nt++) {
            int c = wn * 64 + nt * 8 + (lane & 3) * 2;
            float b0 = bias[c], b1 = bias[c + 1];
#pragma unroll
            for (int h = 0; h < 2; h++) {
                int r = rowBase + wm * 32 + mt * 16 + (lane >> 2) + h * 8;
                if (r < M) {
                    float v0 = acc[mt][nt][2 * h + 0] + b0;
                    float v1 = acc[mt][nt][2 * h + 1] + b1;
                    *(float2*)(Cf + (size_t)r * ncols + c) = make_float2(v0, v1);
                }
            }
        }
}

// ---------------- edge kernels (byte-exact R8 + node range) ------------------
__global__ __launch_bounds__(256) void edge128_k(
    const float* __restrict__ qp, const float* __restrict__ a,
    const float* __restrict__ bg, int nodeBase, int nodeCount)
{
    int gw = nodeBase + ((blockIdx.x * 256 + threadIdx.x) >> 5);
    if (gw >= nodeBase + nodeCount || gw >= NN) return;
    int lane = threadIdx.x & 31;
    int c = lane * 4;
    float4 qv = *(const float4*)(qp + (size_t)gw * 256 + c);
    float4 av = *(const float4*)(a + c);
    float ax = 0.f, ay = 0.f, az = 0.f, aw = 0.f;
    float denom = 0.f;
    int i = g_rowptr[gw];
    int end = g_rowptr[gw + 1];
    if (i < end) {
        int s = g_esrc[i];
        float4 pv = *(const float4*)(qp + (size_t)s * 256 + 128 + c);
        while (1) {
            float4 pvn;
            if (i + 1 < end) {
                int sn = g_esrc[i + 1];
                pvn = *(const float4*)(qp + (size_t)sn * 256 + 128 + c);
            }
            float tx = qv.x + pv.x; tx = tx > 0.f ? tx : 0.2f * tx;
            float ty = qv.y + pv.y; ty = ty > 0.f ? ty : 0.2f * ty;
            float tz = qv.z + pv.z; tz = tz > 0.f ? tz : 0.2f * tz;
            float tw = qv.w + pv.w; tw = tw > 0.f ? tw : 0.2f * tw;
            float part = fmaf(tx, av.x, fmaf(ty, av.y, fmaf(tz, av.z, tw * av.w)));
#pragma unroll
            for (int off = 16; off > 0; off >>= 1)
                part += __shfl_xor_sync(0xffffffffu, part, off);
            float es = __expf(part);
            denom += es;
            ax = fmaf(es, pv.x, ax);
            ay = fmaf(es, pv.y, ay);
            az = fmaf(es, pv.z, az);
            aw = fmaf(es, pv.w, aw);
            i++;
            if (i >= end) break;
            pv = pvn;
        }
    }
    float inv = denom > 0.f ? 1.0f / denom : 0.f;
    float4 bv = *(const float4*)(bg + c);
    float o[4];
    o[0] = gelu_f(fmaf(ax, inv, bv.x));
    o[1] = gelu_f(fmaf(ay, inv, bv.y));
    o[2] = gelu_f(fmaf(az, inv, bv.z));
    o[3] = gelu_f(fmaf(aw, inv, bv.w));
    __half h[4], l[4];
#pragma unroll
    for (int j = 0; j < 4; j++) split_h(o[j], h[j], l[j]);
    __half2 hh0; hh0.x = h[0]; hh0.y = h[1];
    __half2 hh1; hh1.x = h[2]; hh1.y = h[3];
    __half2 ll0; ll0.x = l[0]; ll0.y = l[1];
    __half2 ll1; ll1.x = l[2]; ll1.y = l[3];
    *(__half2*)(g_m2hi + (size_t)gw * 128 + c) = hh0;
    *(__half2*)(g_m2hi + (size_t)gw * 128 + c + 2) = hh1;
    *(__half2*)(g_m2lo + (size_t)gw * 128 + c) = ll0;
    *(__half2*)(g_m2lo + (size_t)gw * 128 + c + 2) = ll1;
}

__global__ __launch_bounds__(256) void edge64_k(
    const float* __restrict__ qp, const float* __restrict__ a,
    const float* __restrict__ bo, float* __restrict__ out)
{
    int gw = (blockIdx.x * 256 + threadIdx.x) >> 5;
    if (gw >= NN) return;
    int lane = threadIdx.x & 31;
    int c = lane * 2;
    float2 qv = *(const float2*)(qp + (size_t)gw * 128 + c);
    float2 av = *(const float2*)(a + c);
    float ax = 0.f, ay = 0.f;
    float denom = 0.f;
    int i = g_rowptr[gw];
    int end = g_rowptr[gw + 1];
    if (i < end) {
        int s = g_esrc[i];
        float2 pv = *(const float2*)(qp + (size_t)s * 128 + 64 + c);
        while (1) {
            float2 pvn;
            if (i + 1 < end) {
                int sn = g_esrc[i + 1];
                pvn = *(const float2*)(qp + (size_t)sn * 128 + 64 + c);
            }
            float tx = qv.x + pv.x; tx = tx > 0.f ? tx : 0.2f * tx;
            float ty = qv.y + pv.y; ty = ty > 0.f ? ty : 0.2f * ty;
            float part = fmaf(tx, av.x, ty * av.y);
#pragma unroll
            for (int off = 16; off > 0; off >>= 1)
                part += __shfl_xor_sync(0xffffffffu, part, off);
            float es = __expf(part);
            denom += es;
            ax = fmaf(es, pv.x, ax);
            ay = fmaf(es, pv.y, ay);
            i++;
            if (i >= end) break;
            pv = pvn;
        }
    }
    float inv = denom > 0.f ? 1.0f / denom : 0.f;
    float2 bv = *(const float2*)(bo + c);
    float2 o;
    o.x = fmaf(ax, inv, bv.x);
    o.y = fmaf(ay, inv, bv.y);
    *(float2*)(out + (size_t)gw * 64 + c) = o;
}

// ---------------- launch ----------------
extern "C" void kernel_launch(void* const* d_in, const int* in_sizes, int n_in,
                              void* d_out, int out_size)
{
    const float* x    = (const float*)d_in[0];
    const float* W0   = (const float*)d_in[1];
    const float* b0   = (const float*)d_in[2];
    const float* Wq1  = (const float*)d_in[3];
    const float* bq1  = (const float*)d_in[4];
    const float* Wp1  = (const float*)d_in[5];
    const float* bp1  = (const float*)d_in[6];
    const float* a1   = (const float*)d_in[7];
    const float* bg2  = (const float*)d_in[8];
    const float* Wq2  = (const float*)d_in[9];
    const float* bq2  = (const float*)d_in[10];
    const float* Wp2  = (const float*)d_in[11];
    const float* bp2  = (const float*)d_in[12];
    const float* a2   = (const float*)d_in[13];
    const float* bout = (const float*)d_in[14];
    const int*   src  = (const int*)d_in[15];
    const int*   dst  = (const int*)d_in[16];
    float* out = (float*)d_out;

    __half *m2hi, *m2lo, *w0t, *wqp1t, *wqp2t;
    float *qp1, *qp2, *bqp1, *bqp2;
    cudaGetSymbolAddress((void**)&m2hi, g_m2hi); cudaGetSymbolAddress((void**)&m2lo, g_m2lo);
    cudaGetSymbolAddress((void**)&w0t, g_w0t);
    cudaGetSymbolAddress((void**)&wqp1t, g_wqp1t);
    cudaGetSymbolAddress((void**)&wqp2t, g_wqp2t);
    cudaGetSymbolAddress((void**)&qp1, g_qp1); cudaGetSymbolAddress((void**)&qp2, g_qp2);
    cudaGetSymbolAddress((void**)&bqp1, g_bqp1); cudaGetSymbolAddress((void**)&bqp2, g_bqp2);

    constexpr int SMEM = 3 * ABUF;   // 104448 B
    cudaFuncSetAttribute(gemm_l1, cudaFuncAttributeMaxDynamicSharedMemorySize, SMEM);
    cudaFuncSetAttribute(gemm_mma, cudaFuncAttributeMaxDynamicSharedMemorySize, SMEM);

    // ---- fork: CSR build + layer-2 weight conversion on side stream ----
    cudaStream_t s2;
    cudaStreamCreateWithFlags(&s2, cudaStreamNonBlocking);
    cudaEvent_t evFork, evJoin, evA, evB;
    cudaEventCreateWithFlags(&evFork, cudaEventDisableTiming);
    cudaEventCreateWithFlags(&evJoin, cudaEventDisableTiming);
    cudaEventCreateWithFlags(&evA, cudaEventDisableTiming);
    cudaEventCreateWithFlags(&evB, cudaEventDisableTiming);

    cudaEventRecord(evFork, 0);
    cudaStreamWaitEvent(s2, evFork, 0);
    zero_k<<<(NN + 255) / 256, 256, 0, s2>>>();
    hist_k<<<(EE + 255) / 256, 256, 0, s2>>>(dst);
    scan_k<<<1, 1024, 0, s2>>>();
    scatter_k<<<(EE + 255) / 256, 256, 0, s2>>>(src, dst);
    convw_k<<<(128 * 128 + 255) / 256, 256, 0, s2>>>(Wq2, Wp2, bq2, bp2, wqp2t, bqp2, 64, 64);
    cudaEventRecord(evJoin, s2);

    // ---- main chain (R8 layout): two conversions, fused layer-1 ----
    convw_k<<<(128 * 128 + 255) / 256, 256>>>(W0, W0, b0, b0, w0t, nullptr, 128, 0);
    convw_k<<<(256 * 128 + 255) / 256, 256>>>(Wq1, Wp1, bq1, bp1, wqp1t, bqp1, 128, 128);

    const int MB = (NN + 127) / 128;       // 391
    const int MB_A = NSPLIT / 128;         // 196
    const int MB_B = MB - MB_A;            // 195

    gemm_l1<<<MB, 256, SMEM>>>(x, w0t, b0, wqp1t, bqp1, qp1, NN);

    // join: edge pass needs the CSR
    cudaStreamWaitEvent(0, evJoin, 0);

    // ---- pipelined edge128 / layer-2 GEMM ----
    edge128_k<<<(NSPLIT * 32 + 255) / 256, 256>>>(qp1, a1, bg2, 0, NSPLIT);
    cudaEventRecord(evA, 0);
    cudaStreamWaitEvent(s2, evA, 0);
    gemm_mma<<<MB_A, 256, SMEM, s2>>>(m2hi, m2lo, wqp2t, bqp2, qp2, NN, 128, 0);
    cudaEventRecord(evB, s2);

    edge128_k<<<((NN - NSPLIT) * 32 + 255) / 256, 256>>>(qp1, a1, bg2, NSPLIT, NN - NSPLIT);
    gemm_mma<<<MB_B, 256, SMEM>>>(m2hi, m2lo, wqp2t, bqp2, qp2, NN, 128, NSPLIT);

    cudaStreamWaitEvent(0, evB, 0);
    edge64_k<<<(NN * 32 + 255) / 256, 256>>>(qp2, a2, bout, out);
}

// round 13
// speedup vs baseline: 1.1702x; 1.0415x over previous
#include <cuda_runtime.h>
#include <cuda_fp16.h>
#include <cstdint>

#define NN 50000
#define EE 800000

// ---------------- scratch (static device globals; no allocs) ----------------
__device__ __half g_m2[NN * 128];
__device__ float g_qp1[NN * 256];   // [node][0:128]=q1, [128:256]=p1
__device__ float g_qp2[NN * 128];   // [node][0:64]=q2, [64:128]=p2
__device__ __half g_w0t[128 * 128];
__device__ __half g_wqp1t[256 * 128];
__device__ __half g_wqp2t[128 * 128];
__device__ float g_bqp1[256];
__device__ float g_bqp2[128];
__device__ int   g_rowptr[NN + 1];
__device__ int   g_cursor[NN];
__device__ int   g_esrc[EE];

__device__ __forceinline__ float gelu_f(float x) {
    return 0.5f * x * (1.0f + erff(x * 0.70710678118654752440f));
}
__device__ __forceinline__ uint32_t smem_u32(const void* p) {
    uint32_t a;
    asm("{ .reg .u64 t; cvta.to.shared.u64 t, %1; cvt.u32.u64 %0, t; }" : "=r"(a) : "l"(p));
    return a;
}
__device__ __forceinline__ void ldsm4(uint32_t& r0, uint32_t& r1, uint32_t& r2, uint32_t& r3, uint32_t addr) {
    asm volatile("ldmatrix.sync.aligned.m8n8.x4.shared.b16 {%0,%1,%2,%3}, [%4];"
                 : "=r"(r0), "=r"(r1), "=r"(r2), "=r"(r3) : "r"(addr));
}
__device__ __forceinline__ void mma_f16(float* c, const uint32_t* a, const uint32_t* b) {
    asm volatile(
        "mma.sync.aligned.m16n8k16.row.col.f32.f16.f16.f32 "
        "{%0,%1,%2,%3}, {%4,%5,%6,%7}, {%8,%9}, {%0,%1,%2,%3};"
        : "+f"(c[0]), "+f"(c[1]), "+f"(c[2]), "+f"(c[3])
        : "r"(a[0]), "r"(a[1]), "r"(a[2]), "r"(a[3]), "r"(b[0]), "r"(b[1]));
}
__device__ __forceinline__ void cp16(uint32_t saddr, const void* gaddr) {
    asm volatile("cp.async.cg.shared.global [%0], [%1], 16;" :: "r"(saddr), "l"(gaddr) : "memory");
}

#define ASTRIDE 136
#define ABUF (128 * ASTRIDE * 2)   // 34816 B per buffer

// single-term fp16 mainloop: acc += A(smem) @ B(smem)^T for warp's 32x64 tile
__device__ __forceinline__ void mainloop_1t(
    uint32_t ah_base, uint32_t bh_base,
    int wm, int wn, int lane, float acc[2][8][4])
{
    const int a_r = (lane & 15);
    const int a_c = (lane >> 4) * 8;
    const int b_r = (lane & 7) + ((lane >> 4) << 3);
    const int b_c = ((lane >> 3) & 1) * 8;
#pragma unroll
    for (int ks = 0; ks < 8; ks++) {
        const int k0 = ks * 16;
        uint32_t ah[2][4];
#pragma unroll
        for (int mt = 0; mt < 2; mt++) {
            uint32_t off = (uint32_t)((wm * 32 + mt * 16 + a_r) * ASTRIDE + k0 + a_c) * 2;
            ldsm4(ah[mt][0], ah[mt][1], ah[mt][2], ah[mt][3], ah_base + off);
        }
        uint32_t bh[8][2];
#pragma unroll
        for (int ng = 0; ng < 4; ng++) {
            uint32_t off = (uint32_t)((wn * 64 + ng * 16 + b_r) * ASTRIDE + k0 + b_c) * 2;
            ldsm4(bh[2 * ng][0], bh[2 * ng][1], bh[2 * ng + 1][0], bh[2 * ng + 1][1], bh_base + off);
        }
#pragma unroll
        for (int mt = 0; mt < 2; mt++)
#pragma unroll
            for (int nt = 0; nt < 8; nt++)
                mma_f16(acc[mt][nt], ah[mt], bh[nt]);
    }
}

// ---------------- CSR build ----------------
__global__ void zero_k() {
    int i = blockIdx.x * blockDim.x + threadIdx.x;
    if (i < NN) g_cursor[i] = 0;
}
__global__ void hist_k(const int* __restrict__ dst) {
    int e = blockIdx.x * blockDim.x + threadIdx.x;
    if (e < EE) atomicAdd(&g_cursor[dst[e]], 1);
}
__global__ __launch_bounds__(1024) void scan_k() {
    __shared__ int warpsum[32];
    __shared__ int s_carry;
    __shared__ int s_tot;
    int tid = threadIdx.x, lane = tid & 31, wid = tid >> 5;
    if (tid == 0) s_carry = 0;
    __syncthreads();
    for (int base = 0; base < NN; base += 8192) {
        int idx0 = base + tid * 8;
        int v[8]; int tot = 0;
#pragma unroll
        for (int j = 0; j < 8; j++) {
            int id = idx0 + j;
            v[j] = (id < NN) ? g_cursor[id] : 0;
            tot += v[j];
        }
        int incl = tot;
#pragma unroll
        for (int off = 1; off < 32; off <<= 1) {
            int t = __shfl_up_sync(0xffffffffu, incl, off);
            if (lane >= off) incl += t;
        }
        if (lane == 31) warpsum[wid] = incl;
        __syncthreads();
        if (wid == 0) {
            int w = warpsum[lane];
            int wi = w;
#pragma unroll
            for (int off = 1; off < 32; off <<= 1) {
                int t = __shfl_up_sync(0xffffffffu, wi, off);
                if (lane >= off) wi += t;
            }
            warpsum[lane] = wi - w;
            if (lane == 31) s_tot = wi;
        }
        __syncthreads();
        int run = s_carry + warpsum[wid] + (incl - tot);
#pragma unroll
        for (int j = 0; j < 8; j++) {
            int id = idx0 + j;
            if (id < NN) { g_rowptr[id] = run; g_cursor[id] = 0; }
            run += v[j];
        }
        __syncthreads();
        if (tid == 0) s_carry += s_tot;
        __syncthreads();
    }
    if (threadIdx.x == 0) g_rowptr[NN] = s_carry;
}
__global__ void scatter_k(const int* __restrict__ src, const int* __restrict__ dst) {
    int e = blockIdx.x * blockDim.x + threadIdx.x;
    if (e < EE) {
        int d = dst[e];
        int pos = g_rowptr[d] + atomicAdd(&g_cursor[d], 1);
        g_esrc[pos] = src[e];
    }
}

// ---------------- conversions ----------------
__global__ void convw_k(const float* __restrict__ Wa, const float* __restrict__ Wb,
                        const float* __restrict__ ba, const float* __restrict__ bb,
                        __half* __restrict__ Wt, float* __restrict__ bc, int na, int nb) {
    int nc = na + nb;
    int i = blockIdx.x * blockDim.x + threadIdx.x;
    if (i < nc * 128) {
        int n = i >> 7, k = i & 127;
        float v = (n < na) ? Wa[(size_t)k * na + n] : Wb[(size_t)k * nb + (n - na)];
        Wt[i] = __float2half_rn(v);
    }
    if (bc && i < nc) bc[i] = (i < na) ? ba[i] : bb[i - na];
}

// ---------------- fused layer-1: qp1 = gelu(x@W0+b0) @ Wqp1 + bqp1 -----------
// Single-fp16 path: x converted in-register, m1 stored fp16 in AH.
__global__ __launch_bounds__(256, 2) void gemm_l1(
    const float* __restrict__ x, const __half* __restrict__ W0t,
    const float* __restrict__ b0, const __half* __restrict__ Wqp1t,
    const float* __restrict__ bqp1, float* __restrict__ qp1, int M)
{
    extern __shared__ char sm[];
    char* AH = sm;
    char* BH = sm + ABUF;

    const int tid = threadIdx.x;
    const int warp = tid >> 5, lane = tid & 31;
    const int wm = warp >> 1, wn = warp & 1;
    const int rowBase = blockIdx.x * 128;

    const uint32_t ah_base = smem_u32(AH);
    const uint32_t bh_base = smem_u32(BH);

    // ---- stage W0 (async) + x (fp32 -> fp16 in regs) ----
#pragma unroll
    for (int it = 0; it < 8; it++) {
        int idx = tid + it * 256;               // 0..2047
        int row = idx >> 4, ch = idx & 15;
        uint32_t so = (uint32_t)(row * ASTRIDE + ch * 8) * 2;
        cp16(bh_base + so, W0t + (size_t)row * 128 + ch * 8);
    }
    asm volatile("cp.async.commit_group;" ::: "memory");
#pragma unroll
    for (int it = 0; it < 8; it++) {
        int idx = tid + it * 256;
        int row = idx >> 4, ch = idx & 15;
        int gr = rowBase + row; if (gr >= M) gr = M - 1;
        float4 v0 = *(const float4*)(x + (size_t)gr * 128 + ch * 8);
        float4 v1 = *(const float4*)(x + (size_t)gr * 128 + ch * 8 + 4);
        __half hh[8];
        hh[0] = __float2half_rn(v0.x); hh[1] = __float2half_rn(v0.y);
        hh[2] = __float2half_rn(v0.z); hh[3] = __float2half_rn(v0.w);
        hh[4] = __float2half_rn(v1.x); hh[5] = __float2half_rn(v1.y);
        hh[6] = __float2half_rn(v1.z); hh[7] = __float2half_rn(v1.w);
        uint32_t so = (uint32_t)(row * ASTRIDE + ch * 8) * 2;
        *(uint4*)(AH + so) = *(const uint4*)hh;
    }
    asm volatile("cp.async.wait_group 0;" ::: "memory");
    __syncthreads();

    float acc[2][8][4];
#pragma unroll
    for (int i = 0; i < 2; i++)
#pragma unroll
        for (int j = 0; j < 8; j++)
#pragma unroll
            for (int k = 0; k < 4; k++) acc[i][j][k] = 0.f;

    // ---- mainloop 1: m1 = x @ W0^T ----
    mainloop_1t(ah_base, bh_base, wm, wn, lane, acc);
    __syncthreads();   // everyone done reading AH

    // ---- epilogue 1: gelu(m1+b0) -> fp16 back into AH ----
#pragma unroll
    for (int mt = 0; mt < 2; mt++)
#pragma unroll
        for (int nt = 0; nt < 8; nt++) {
            int c = wn * 64 + nt * 8 + (lane & 3) * 2;
            float bb0 = b0[c], bb1 = b0[c + 1];
#pragma unroll
            for (int h = 0; h < 2; h++) {
                int r = wm * 32 + mt * 16 + (lane >> 2) + h * 8;
                float v0 = gelu_f(acc[mt][nt][2 * h + 0] + bb0);
                float v1 = gelu_f(acc[mt][nt][2 * h + 1] + bb1);
                uint32_t so = (uint32_t)(r * ASTRIDE + c) * 2;
                __half2 hh;
                hh.x = __float2half_rn(v0);
                hh.y = __float2half_rn(v1);
                *(__half2*)(AH + so) = hh;
            }
        }
    __syncthreads();

    // ---- stage 2: two column-halves of qp1 = m1 @ Wqp1^T ----
#pragma unroll
    for (int cb = 0; cb < 2; cb++) {
#pragma unroll
        for (int it = 0; it < 8; it++) {
            int idx = tid + it * 256;
            int row = idx >> 4, ch = idx & 15;
            uint32_t so = (uint32_t)(row * ASTRIDE + ch * 8) * 2;
            cp16(bh_base + so, Wqp1t + (size_t)(cb * 128 + row) * 128 + ch * 8);
        }
        asm volatile("cp.async.commit_group;" ::: "memory");
        asm volatile("cp.async.wait_group 0;" ::: "memory");
        __syncthreads();

#pragma unroll
        for (int i = 0; i < 2; i++)
#pragma unroll
            for (int j = 0; j < 8; j++)
#pragma unroll
                for (int k = 0; k < 4; k++) acc[i][j][k] = 0.f;
        mainloop_1t(ah_base, bh_base, wm, wn, lane, acc);

#pragma unroll
        for (int mt = 0; mt < 2; mt++)
#pragma unroll
            for (int nt = 0; nt < 8; nt++) {
                int c = cb * 128 + wn * 64 + nt * 8 + (lane & 3) * 2;
                float bb0 = bqp1[c], bb1 = bqp1[c + 1];
#pragma unroll
                for (int h = 0; h < 2; h++) {
                    int r = rowBase + wm * 32 + mt * 16 + (lane >> 2) + h * 8;
                    if (r < M) {
                        float v0 = acc[mt][nt][2 * h + 0] + bb0;
                        float v1 = acc[mt][nt][2 * h + 1] + bb1;
                        *(float2*)(qp1 + (size_t)r * 256 + c) = make_float2(v0, v1);
                    }
                }
            }
        if (cb == 0) __syncthreads();   // before overwriting BH
    }
}

// ---------------- layer-2 GEMM: qp2 = m2(fp16) @ Wqp2^T + bqp2 ---------------
__global__ __launch_bounds__(256, 2) void gemm_mma(
    const __half* __restrict__ A, const __half* __restrict__ Bh,
    const float* __restrict__ bias, float* __restrict__ Cf, int M, int ncols)
{
    extern __shared__ char sm[];
    char* AH = sm;
    char* BH = sm + ABUF;

    const int tid = threadIdx.x;
    const int warp = tid >> 5, lane = tid & 31;
    const int wm = warp >> 1, wn = warp & 1;
    const int rowBase = blockIdx.x * 128;

    const uint32_t ah_base = smem_u32(AH);
    const uint32_t bh_base = smem_u32(BH);

#pragma unroll
    for (int it = 0; it < 8; it++) {
        int idx = tid + it * 256;
        int row = idx >> 4, ch = idx & 15;
        int gr = rowBase + row; if (gr >= M) gr = M - 1;
        uint32_t so = (uint32_t)(row * ASTRIDE + ch * 8) * 2;
        cp16(ah_base + so, A + (size_t)gr * 128 + ch * 8);
        cp16(bh_base + so, Bh + (size_t)row * 128 + ch * 8);
    }
    asm volatile("cp.async.commit_group;" ::: "memory");
    asm volatile("cp.async.wait_group 0;" ::: "memory");
    __syncthreads();

    float acc[2][8][4];
#pragma unroll
    for (int i = 0; i < 2; i++)
#pragma unroll
        for (int j = 0; j < 8; j++)
#pragma unroll
            for (int k = 0; k < 4; k++) acc[i][j][k] = 0.f;
    mainloop_1t(ah_base, bh_base, wm, wn, lane, acc);

#pragma unroll
    for (int mt = 0; mt < 2; mt++)
#pragma unroll
        for (int nt = 0; nt < 8; nt++) {
            int c = wn * 64 + nt * 8 + (lane & 3) * 2;
            float b0 = bias[c], b1 = bias[c + 1];
#pragma unroll
            for (int h = 0; h < 2; h++) {
                int r = rowBase + wm * 32 + mt * 16 + (lane >> 2) + h * 8;
                if (r < M) {
                    float v0 = acc[mt][nt][2 * h + 0] + b0;
                    float v1 = acc[mt][nt][2 * h + 1] + b1;
                    *(float2*)(Cf + (size_t)r * ncols + c) = make_float2(v0, v1);
                }
            }
        }
}

// ---------------- edge kernels: one warp per dst node (R8 formulation) --------
__global__ __launch_bounds__(256) void edge128_k(
    const float* __restrict__ qp, const float* __restrict__ a,
    const float* __restrict__ bg)
{
    int gw = (blockIdx.x * 256 + threadIdx.x) >> 5;
    if (gw >= NN) return;
    int lane = threadIdx.x & 31;
    int c = lane * 4;
    float4 qv = *(const float4*)(qp + (size_t)gw * 256 + c);
    float4 av = *(const float4*)(a + c);
    float ax = 0.f, ay = 0.f, az = 0.f, aw = 0.f;
    float denom = 0.f;
    int i = g_rowptr[gw];
    int end = g_rowptr[gw + 1];
    if (i < end) {
        int s = g_esrc[i];
        float4 pv = *(const float4*)(qp + (size_t)s * 256 + 128 + c);
        while (1) {
            float4 pvn;
            if (i + 1 < end) {
                int sn = g_esrc[i + 1];
                pvn = *(const float4*)(qp + (size_t)sn * 256 + 128 + c);
            }
            float tx = qv.x + pv.x; tx = tx > 0.f ? tx : 0.2f * tx;
            float ty = qv.y + pv.y; ty = ty > 0.f ? ty : 0.2f * ty;
            float tz = qv.z + pv.z; tz = tz > 0.f ? tz : 0.2f * tz;
            float tw = qv.w + pv.w; tw = tw > 0.f ? tw : 0.2f * tw;
            float part = fmaf(tx, av.x, fmaf(ty, av.y, fmaf(tz, av.z, tw * av.w)));
#pragma unroll
            for (int off = 16; off > 0; off >>= 1)
                part += __shfl_xor_sync(0xffffffffu, part, off);
            float es = __expf(part);
            denom += es;
            ax = fmaf(es, pv.x, ax);
            ay = fmaf(es, pv.y, ay);
            az = fmaf(es, pv.z, az);
            aw = fmaf(es, pv.w, aw);
            i++;
            if (i >= end) break;
            pv = pvn;
        }
    }
    float inv = denom > 0.f ? 1.0f / denom : 0.f;
    float4 bv = *(const float4*)(bg + c);
    float o[4];
    o[0] = gelu_f(fmaf(ax, inv, bv.x));
    o[1] = gelu_f(fmaf(ay, inv, bv.y));
    o[2] = gelu_f(fmaf(az, inv, bv.z));
    o[3] = gelu_f(fmaf(aw, inv, bv.w));
    __half2 hh0, hh1;
    hh0.x = __float2half_rn(o[0]); hh0.y = __float2half_rn(o[1]);
    hh1.x = __float2half_rn(o[2]); hh1.y = __float2half_rn(o[3]);
    *(__half2*)(g_m2 + (size_t)gw * 128 + c) = hh0;
    *(__half2*)(g_m2 + (size_t)gw * 128 + c + 2) = hh1;
}

__global__ __launch_bounds__(256) void edge64_k(
    const float* __restrict__ qp, const float* __restrict__ a,
    const float* __restrict__ bo, float* __restrict__ out)
{
    int gw = (blockIdx.x * 256 + threadIdx.x) >> 5;
    if (gw >= NN) return;
    int lane = threadIdx.x & 31;
    int c = lane * 2;
    float2 qv = *(const float2*)(qp + (size_t)gw * 128 + c);
    float2 av = *(const float2*)(a + c);
    float ax = 0.f, ay = 0.f;
    float denom = 0.f;
    int i = g_rowptr[gw];
    int end = g_rowptr[gw + 1];
    if (i < end) {
        int s = g_esrc[i];
        float2 pv = *(const float2*)(qp + (size_t)s * 128 + 64 + c);
        while (1) {
            float2 pvn;
            if (i + 1 < end) {
                int sn = g_esrc[i + 1];
                pvn = *(const float2*)(qp + (size_t)sn * 128 + 64 + c);
            }
            float tx = qv.x + pv.x; tx = tx > 0.f ? tx : 0.2f * tx;
            float ty = qv.y + pv.y; ty = ty > 0.f ? ty : 0.2f * ty;
            float part = fmaf(tx, av.x, ty * av.y);
#pragma unroll
            for (int off = 16; off > 0; off >>= 1)
                part += __shfl_xor_sync(0xffffffffu, part, off);
            float es = __expf(part);
            denom += es;
            ax = fmaf(es, pv.x, ax);
            ay = fmaf(es, pv.y, ay);
            i++;
            if (i >= end) break;
            pv = pvn;
        }
    }
    float inv = denom > 0.f ? 1.0f / denom : 0.f;
    float2 bv = *(const float2*)(bo + c);
    float2 o;
    o.x = fmaf(ax, inv, bv.x);
    o.y = fmaf(ay, inv, bv.y);
    *(float2*)(out + (size_t)gw * 64 + c) = o;
}

// ---------------- launch ----------------
extern "C" void kernel_launch(void* const* d_in, const int* in_sizes, int n_in,
                              void* d_out, int out_size)
{
    const float* x    = (const float*)d_in[0];
    const float* W0   = (const float*)d_in[1];
    const float* b0   = (const float*)d_in[2];
    const float* Wq1  = (const float*)d_in[3];
    const float* bq1  = (const float*)d_in[4];
    const float* Wp1  = (const float*)d_in[5];
    const float* bp1  = (const float*)d_in[6];
    const float* a1   = (const float*)d_in[7];
    const float* bg2  = (const float*)d_in[8];
    const float* Wq2  = (const float*)d_in[9];
    const float* bq2  = (const float*)d_in[10];
    const float* Wp2  = (const float*)d_in[11];
    const float* bp2  = (const float*)d_in[12];
    const float* a2   = (const float*)d_in[13];
    const float* bout = (const float*)d_in[14];
    const int*   src  = (const int*)d_in[15];
    const int*   dst  = (const int*)d_in[16];
    float* out = (float*)d_out;

    __half *m2, *w0t, *wqp1t, *wqp2t;
    float *qp1, *qp2, *bqp1, *bqp2;
    cudaGetSymbolAddress((void**)&m2, g_m2);
    cudaGetSymbolAddress((void**)&w0t, g_w0t);
    cudaGetSymbolAddress((void**)&wqp1t, g_wqp1t);
    cudaGetSymbolAddress((void**)&wqp2t, g_wqp2t);
    cudaGetSymbolAddress((void**)&qp1, g_qp1); cudaGetSymbolAddress((void**)&qp2, g_qp2);
    cudaGetSymbolAddress((void**)&bqp1, g_bqp1); cudaGetSymbolAddress((void**)&bqp2, g_bqp2);

    constexpr int SMEM = 2 * ABUF;   // 69632 B
    cudaFuncSetAttribute(gemm_l1, cudaFuncAttributeMaxDynamicSharedMemorySize, SMEM);
    cudaFuncSetAttribute(gemm_mma, cudaFuncAttributeMaxDynamicSharedMemorySize, SMEM);

    // ---- fork: CSR build + layer-2 weight conversion on side stream ----
    cudaStream_t s2;
    cudaStreamCreateWithFlags(&s2, cudaStreamNonBlocking);
    cudaEvent_t evFork, evJoin;
    cudaEventCreateWithFlags(&evFork, cudaEventDisableTiming);
    cudaEventCreateWithFlags(&evJoin, cudaEventDisableTiming);

    cudaEventRecord(evFork, 0);
    cudaStreamWaitEvent(s2, evFork, 0);
    zero_k<<<(NN + 255) / 256, 256, 0, s2>>>();
    hist_k<<<(EE + 255) / 256, 256, 0, s2>>>(dst);
    scan_k<<<1, 1024, 0, s2>>>();
    scatter_k<<<(EE + 255) / 256, 256, 0, s2>>>(src, dst);
    convw_k<<<(128 * 128 + 255) / 256, 256, 0, s2>>>(Wq2, Wp2, bq2, bp2, wqp2t, bqp2, 64, 64);
    cudaEventRecord(evJoin, s2);

    // ---- main chain ----
    convw_k<<<(128 * 128 + 255) / 256, 256>>>(W0, W0, b0, b0, w0t, nullptr, 128, 0);
    convw_k<<<(256 * 128 + 255) / 256, 256>>>(Wq1, Wp1, bq1, bp1, wqp1t, bqp1, 128, 128);

    const int MB = (NN + 127) / 128;

    gemm_l1<<<MB, 256, SMEM>>>(x, w0t, b0, wqp1t, bqp1, qp1, NN);

    // join: edge pass needs the CSR
    cudaStreamWaitEvent(0, evJoin, 0);
    edge128_k<<<(NN * 32 + 255) / 256, 256>>>(qp1, a1, bg2);       // m2 (fp16)

    gemm_mma<<<MB, 256, SMEM>>>(m2, wqp2t, bqp2, qp2, NN, 128);
    edge64_k<<<(NN * 32 + 255) / 256, 256>>>(qp2, a2, bout, out);
}